// round 10
// baseline (speedup 1.0000x reference)
#include <cuda_runtime.h>
#include <cuda_bf16.h>
#include <cstdint>

#define Bn 4
#define Sn 2048
#define Dn 768
#define Hn 12
#define Kn 64
#define NELEM (Bn * Hn * Sn * Kn)

// Scratch device globals (no cudaMalloc allowed).
__device__ __nv_bfloat16 g_qh[NELEM], g_ql[NELEM];
__device__ __nv_bfloat16 g_kh[NELEM], g_kl[NELEM];
__device__ __nv_bfloat16 g_vh[NELEM], g_vl[NELEM];
__device__ __nv_bfloat16 g_oh[NELEM], g_ol[NELEM];
__device__ __nv_bfloat16 g_xsh[Bn * Sn * Dn], g_xsl[Bn * Sn * Dn];
__device__ __nv_bfloat16 g_wsh[Dn * Dn], g_wsl[Dn * Dn];

// ---------------------------------------------------------------------------
// helpers
// ---------------------------------------------------------------------------
__device__ __forceinline__ uint32_t smem_u32(const void* p) {
    uint32_t a;
    asm("{ .reg .u64 t; cvta.to.shared.u64 t, %1; cvt.u32.u64 %0, t; }" : "=r"(a) : "l"(p));
    return a;
}
__device__ __forceinline__ void ldsm_x4(uint32_t (&r)[4], uint32_t addr) {
    asm volatile("ldmatrix.sync.aligned.m8n8.x4.shared.b16 {%0,%1,%2,%3}, [%4];"
                 : "=r"(r[0]), "=r"(r[1]), "=r"(r[2]), "=r"(r[3]) : "r"(addr));
}
__device__ __forceinline__ void ldsm_x4t(uint32_t (&r)[4], uint32_t addr) {
    asm volatile("ldmatrix.sync.aligned.m8n8.x4.trans.shared.b16 {%0,%1,%2,%3}, [%4];"
                 : "=r"(r[0]), "=r"(r[1]), "=r"(r[2]), "=r"(r[3]) : "r"(addr));
}
__device__ __forceinline__ void mma_bf16(float (&d)[4], const uint32_t (&a)[4],
                                         const uint32_t b0, const uint32_t b1) {
    asm volatile(
        "mma.sync.aligned.m16n8k16.row.col.f32.bf16.bf16.f32 "
        "{%0,%1,%2,%3}, {%4,%5,%6,%7}, {%8,%9}, {%0,%1,%2,%3};"
        : "+f"(d[0]), "+f"(d[1]), "+f"(d[2]), "+f"(d[3])
        : "r"(a[0]), "r"(a[1]), "r"(a[2]), "r"(a[3]), "r"(b0), "r"(b1));
}
__device__ __forceinline__ void split2(float x, float y, uint32_t& h, uint32_t& l) {
    __nv_bfloat16 hx = __float2bfloat16(x), hy = __float2bfloat16(y);
    __nv_bfloat16 lx = __float2bfloat16(x - __bfloat162float(hx));
    __nv_bfloat16 ly = __float2bfloat16(y - __bfloat162float(hy));
    __nv_bfloat162 hh = __halves2bfloat162(hx, hy);
    __nv_bfloat162 ll = __halves2bfloat162(lx, ly);
    h = *(uint32_t*)&hh;
    l = *(uint32_t*)&ll;
}
__device__ __forceinline__ void cpa16(uint32_t dst, const void* src) {
    asm volatile("cp.async.cg.shared.global [%0], [%1], 16;" :: "r"(dst), "l"(src) : "memory");
}
__device__ __forceinline__ void cp_commit() { asm volatile("cp.async.commit_group;" ::: "memory"); }
__device__ __forceinline__ void cp_wait1() { asm volatile("cp.async.wait_group 1;" ::: "memory"); }

// ---------------------------------------------------------------------------
// Presplit kernels
// ---------------------------------------------------------------------------
__global__ void split_flat(const float* __restrict__ in, __nv_bfloat16* __restrict__ oh,
                           __nv_bfloat16* __restrict__ ol, int n4) {
    int i = blockIdx.x * blockDim.x + threadIdx.x;
    if (i >= n4) return;
    float4 v = ((const float4*)in)[i];
    uint32_t h0, l0, h1, l1;
    split2(v.x, v.y, h0, l0);
    split2(v.z, v.w, h1, l1);
    ((uint2*)oh)[i] = make_uint2(h0, h1);
    ((uint2*)ol)[i] = make_uint2(l0, l1);
}

// W [H][D][K] -> Wt [D][H*K] (k-major for the proj GEMM), split hi/lo
__global__ void split_wqkv(const float* __restrict__ W, __nv_bfloat16* __restrict__ oh,
                           __nv_bfloat16* __restrict__ ol) {
    int i = blockIdx.x * blockDim.x + threadIdx.x;  // over 768*384 col-pairs
    if (i >= Dn * (Dn / 2)) return;
    int d = i / (Dn / 2), c = (i % (Dn / 2)) * 2;
    int h = c >> 6, k = c & 63;
    float2 v = *(const float2*)(W + ((size_t)h * Dn + d) * Kn + k);
    uint32_t hh, ll;
    split2(v.x, v.y, hh, ll);
    *(uint32_t*)(oh + (size_t)d * Dn + c) = hh;
    *(uint32_t*)(ol + (size_t)d * Dn + c) = ll;
}

// ===========================================================================
// Attention: 256 threads / 8 warps. Warp (qw, half): qw = wid>>1 owns q rows
// [32qw, 32qw+32), half = wid&1 owns S cols / kv rows [64half, 64half+64).
// Q-hi fragments hoisted to registers; K/V double-buffered via cp.async.
// No-max softmax.
// ===========================================================================
#define QS 72
#define TILE_E (128 * QS)
#define TILE_B (TILE_E * 2)
#define SM_MAXB (10 * TILE_B)
#define ATTN_SMEM (SM_MAXB + 256 * 4)

__global__ __launch_bounds__(256, 1) void attn_kernel(const float* __restrict__ mask) {
    extern __shared__ __nv_bfloat16 smbf[];
    const uint32_t smb = smem_u32(smbf);
    float* mbuf = (float*)((char*)smbf + SM_MAXB);
    float* Obuf = (float*)(smbf + 2 * TILE_E);  // stage area reused post-loop

    const int tid = threadIdx.x;
    const int wid = tid >> 5, lane = tid & 31;
    const int qw = wid >> 1, half = wid & 1;
    const int cb = half * 64;
    const int l16 = lane & 15;
    const int g = lane >> 3;
    const int r0 = lane >> 2;
    const int c2 = (lane & 3) * 2;
    const int qt = blockIdx.x, hd = blockIdx.y, b = blockIdx.z;
    const size_t bh = (size_t)(b * Hn + hd) * Sn;
    const int qr0 = qw * 32;

    const int ld_c = (tid & 7) * 8;

    // Q tile hi/lo into smem (once), then hoist hi fragments to registers.
    {
        const __nv_bfloat16* qh = g_qh + (bh + (size_t)qt * 128) * Kn;
        const __nv_bfloat16* ql = g_ql + (bh + (size_t)qt * 128) * Kn;
#pragma unroll
        for (int rep = 0; rep < 4; ++rep) {
            int r = (tid + rep * 256) >> 3;
            *(uint4*)(smbf + r * QS + ld_c) = *(const uint4*)(qh + r * 64 + ld_c);
            *(uint4*)(smbf + TILE_E + r * QS + ld_c) = *(const uint4*)(ql + r * 64 + ld_c);
        }
    }
    __syncthreads();

    uint32_t aQh[4][2][4];  // [ks][mi][frag] — hi terms, hoisted
#pragma unroll
    for (int ks = 0; ks < 4; ++ks)
#pragma unroll
        for (int mi = 0; mi < 2; ++mi) {
            const uint32_t aoff =
                (uint32_t)(((qr0 + mi * 16 + l16) * QS + ks * 16 + (lane >> 4) * 8) * 2);
            ldsm_x4(aQh[ks][mi], smb + aoff);
        }

    auto issue_tile = [&](int kt2, int st) {
        const __nv_bfloat16* kh = g_kh + (bh + (size_t)kt2 * 128) * Kn;
        const __nv_bfloat16* kl = g_kl + (bh + (size_t)kt2 * 128) * Kn;
        const __nv_bfloat16* vh = g_vh + (bh + (size_t)kt2 * 128) * Kn;
        const __nv_bfloat16* vl = g_vl + (bh + (size_t)kt2 * 128) * Kn;
        const uint32_t base = smb + (uint32_t)(2 + st * 4) * TILE_B;
#pragma unroll
        for (int rep = 0; rep < 4; ++rep) {
            int r = (tid + rep * 256) >> 3;
            uint32_t off = (uint32_t)(r * QS + ld_c) * 2;
            cpa16(base + off, kh + r * 64 + ld_c);
            cpa16(base + TILE_B + off, kl + r * 64 + ld_c);
            cpa16(base + TILE_B * 2 + off, vh + r * 64 + ld_c);
            cpa16(base + TILE_B * 3 + off, vl + r * 64 + ld_c);
        }
    };

    issue_tile(0, 0);
    cp_commit();
    issue_tile(1, 1);
    cp_commit();

    float oacc[2][8][4];
#pragma unroll
    for (int mi = 0; mi < 2; ++mi)
#pragma unroll
        for (int n = 0; n < 8; ++n)
#pragma unroll
            for (int j = 0; j < 4; ++j) oacc[mi][n][j] = 0.f;
    float lA[2][2] = {{0.f, 0.f}, {0.f, 0.f}};

    const float* mp[2];
    mp[0] = mask + (size_t)(qt * 128 + qr0 + r0) * Sn;
    mp[1] = mp[0] + 16 * Sn;
    const float scale = 0.125f;

    for (int kt = 0; kt < Sn / 128; ++kt) {
        const int st = kt & 1;
        const uint32_t sKh = smb + (uint32_t)(2 + st * 4) * TILE_B;
        const uint32_t sKl = sKh + TILE_B;
        const uint32_t sVh = sKh + TILE_B * 2;
        const uint32_t sVl = sKh + TILE_B * 3;
        const uint32_t sQl = smb + TILE_E * 2;

        cp_wait1();
        __syncthreads();

        // ---- S = Q @ K^T  (m32 x n64 per warp, 3 split terms) ----
        float sacc[2][8][4];
#pragma unroll
        for (int mi = 0; mi < 2; ++mi)
#pragma unroll
            for (int n = 0; n < 8; ++n)
#pragma unroll
                for (int j = 0; j < 4; ++j) sacc[mi][n][j] = 0.f;

#pragma unroll
        for (int ks = 0; ks < 4; ++ks) {
            uint32_t aql[2][4];
#pragma unroll
            for (int mi = 0; mi < 2; ++mi) {
                const uint32_t aoff =
                    (uint32_t)(((qr0 + mi * 16 + l16) * QS + ks * 16 + (lane >> 4) * 8) * 2);
                ldsm_x4(aql[mi], sQl + aoff);
            }
            uint32_t rh[4][4], rl[4][4];
#pragma unroll
            for (int n2 = 0; n2 < 4; ++n2) {
                const uint32_t boff =
                    (uint32_t)(((cb + n2 * 16 + (g >> 1) * 8 + (lane & 7)) * QS +
                                ks * 16 + (g & 1) * 8) * 2);
                ldsm_x4(rh[n2], sKh + boff);
                ldsm_x4(rl[n2], sKl + boff);
            }
            // term 1: qh*kh — 16 independent chains
#pragma unroll
            for (int mi = 0; mi < 2; ++mi)
#pragma unroll
                for (int n2 = 0; n2 < 4; ++n2) {
                    mma_bf16(sacc[mi][2 * n2], aQh[ks][mi], rh[n2][0], rh[n2][1]);
                    mma_bf16(sacc[mi][2 * n2 + 1], aQh[ks][mi], rh[n2][2], rh[n2][3]);
                }
            // term 2: qh*kl
#pragma unroll
            for (int mi = 0; mi < 2; ++mi)
#pragma unroll
                for (int n2 = 0; n2 < 4; ++n2) {
                    mma_bf16(sacc[mi][2 * n2], aQh[ks][mi], rl[n2][0], rl[n2][1]);
                    mma_bf16(sacc[mi][2 * n2 + 1], aQh[ks][mi], rl[n2][2], rl[n2][3]);
                }
            // term 3: ql*kh
#pragma unroll
            for (int mi = 0; mi < 2; ++mi)
#pragma unroll
                for (int n2 = 0; n2 < 4; ++n2) {
                    mma_bf16(sacc[mi][2 * n2], aql[mi], rh[n2][0], rh[n2][1]);
                    mma_bf16(sacc[mi][2 * n2 + 1], aql[mi], rh[n2][2], rh[n2][3]);
                }
        }

        // ---- scale + mask bias + exp (no max subtraction) ----
#pragma unroll
        for (int mi = 0; mi < 2; ++mi)
#pragma unroll
            for (int n = 0; n < 8; ++n) {
                const int col = kt * 128 + cb + n * 8 + c2;
                float2 mv0 = __ldg((const float2*)(mp[mi] + col));
                float2 mv1 = __ldg((const float2*)(mp[mi] + 8 * Sn + col));
                sacc[mi][n][0] = __expf(fmaf(sacc[mi][n][0], scale, (1.f - mv0.x) * -1e9f));
                sacc[mi][n][1] = __expf(fmaf(sacc[mi][n][1], scale, (1.f - mv0.y) * -1e9f));
                sacc[mi][n][2] = __expf(fmaf(sacc[mi][n][2], scale, (1.f - mv1.x) * -1e9f));
                sacc[mi][n][3] = __expf(fmaf(sacc[mi][n][3], scale, (1.f - mv1.y) * -1e9f));
                lA[mi][0] += sacc[mi][n][0] + sacc[mi][n][1];
                lA[mi][1] += sacc[mi][n][2] + sacc[mi][n][3];
            }

        // ---- O += P @ V_half  (m32 x v64, kv64, 3 split terms) ----
#pragma unroll
        for (int j = 0; j < 4; ++j) {
            uint32_t ah[2][4], al[2][4];
#pragma unroll
            for (int mi = 0; mi < 2; ++mi) {
                split2(sacc[mi][2 * j][0], sacc[mi][2 * j][1], ah[mi][0], al[mi][0]);
                split2(sacc[mi][2 * j][2], sacc[mi][2 * j][3], ah[mi][1], al[mi][1]);
                split2(sacc[mi][2 * j + 1][0], sacc[mi][2 * j + 1][1], ah[mi][2], al[mi][2]);
                split2(sacc[mi][2 * j + 1][2], sacc[mi][2 * j + 1][3], ah[mi][3], al[mi][3]);
            }
            uint32_t rh[4][4], rl[4][4];
#pragma unroll
            for (int nv2 = 0; nv2 < 4; ++nv2) {
                const uint32_t voff =
                    (uint32_t)(((cb + j * 16 + (g & 1) * 8 + (lane & 7)) * QS +
                                nv2 * 16 + (g >> 1) * 8) * 2);
                ldsm_x4t(rh[nv2], sVh + voff);
                ldsm_x4t(rl[nv2], sVl + voff);
            }
#pragma unroll
            for (int mi = 0; mi < 2; ++mi)
#pragma unroll
                for (int nv2 = 0; nv2 < 4; ++nv2) {
                    mma_bf16(oacc[mi][2 * nv2], ah[mi], rh[nv2][0], rh[nv2][1]);
                    mma_bf16(oacc[mi][2 * nv2 + 1], ah[mi], rh[nv2][2], rh[nv2][3]);
                }
#pragma unroll
            for (int mi = 0; mi < 2; ++mi)
#pragma unroll
                for (int nv2 = 0; nv2 < 4; ++nv2) {
                    mma_bf16(oacc[mi][2 * nv2], ah[mi], rl[nv2][0], rl[nv2][1]);
                    mma_bf16(oacc[mi][2 * nv2 + 1], ah[mi], rl[nv2][2], rl[nv2][3]);
                }
#pragma unroll
            for (int mi = 0; mi < 2; ++mi)
#pragma unroll
                for (int nv2 = 0; nv2 < 4; ++nv2) {
                    mma_bf16(oacc[mi][2 * nv2], al[mi], rh[nv2][0], rh[nv2][1]);
                    mma_bf16(oacc[mi][2 * nv2 + 1], al[mi], rh[nv2][2], rh[nv2][3]);
                }
        }

        __syncthreads();  // stage st fully consumed
        if (kt + 2 < Sn / 128) issue_tile(kt + 2, st);
        cp_commit();
    }

    // ---- final l reduction, merge halves, normalize, store ----
#pragma unroll
    for (int mi = 0; mi < 2; ++mi)
#pragma unroll
        for (int w = 1; w < 4; w <<= 1) {
            lA[mi][0] += __shfl_xor_sync(0xffffffffu, lA[mi][0], w);
            lA[mi][1] += __shfl_xor_sync(0xffffffffu, lA[mi][1], w);
        }
    {
        float* Ow = Obuf + (size_t)half * 128 * 64;
#pragma unroll
        for (int mi = 0; mi < 2; ++mi) {
            const int rb = qr0 + mi * 16 + r0;
#pragma unroll
            for (int nv = 0; nv < 8; ++nv) {
                *(float2*)(Ow + rb * 64 + nv * 8 + c2) =
                    make_float2(oacc[mi][nv][0], oacc[mi][nv][1]);
                *(float2*)(Ow + (rb + 8) * 64 + nv * 8 + c2) =
                    make_float2(oacc[mi][nv][2], oacc[mi][nv][3]);
            }
            if ((lane & 3) == 0) {
                mbuf[rb * 2 + half] = lA[mi][0];
                mbuf[(rb + 8) * 2 + half] = lA[mi][1];
            }
        }
    }
    __syncthreads();
#pragma unroll
    for (int rep = 0; rep < 16; ++rep) {
        int idx = tid + rep * 256;
        int r = idx >> 5, cc = (idx & 31) * 2;
        float2 a = *(float2*)(Obuf + r * 64 + cc);
        float2 bb = *(float2*)(Obuf + (128 + r) * 64 + cc);
        float inv = 1.f / (mbuf[r * 2] + mbuf[r * 2 + 1]);
        uint32_t hv, lv;
        split2((a.x + bb.x) * inv, (a.y + bb.y) * inv, hv, lv);
        size_t off = (bh + (size_t)(qt * 128 + r)) * Kn + cc;
        *(uint32_t*)(g_oh + off) = hv;
        *(uint32_t*)(g_ol + off) = lv;
    }
}

// ===========================================================================
// mma.sync GEMM core: C[128 x 128] tile, BK=32, 8 warps (m32 x n64 each).
// All inputs pre-split bf16.
// ===========================================================================
#define AS 40
#define BSS 136

struct MmaCtx {
    int wm, wn, l16, grp, lane;
};

__device__ __forceinline__ void mma_kblock(float (&acc)[2][8][4],
                                           uint32_t sAh, uint32_t sAl,
                                           uint32_t sBh, uint32_t sBl,
                                           const MmaCtx& c) {
#pragma unroll
    for (int ks = 0; ks < 32; ks += 16) {
        uint32_t ah[2][4], al[2][4];
#pragma unroll
        for (int mi = 0; mi < 2; ++mi) {
            const uint32_t aoff =
                (uint32_t)(((c.wm + mi * 16 + c.l16) * AS + ks + (c.lane >> 4) * 8) * 2);
            ldsm_x4(ah[mi], sAh + aoff);
            ldsm_x4(al[mi], sAl + aoff);
        }
        uint32_t bh[8][2], bl[8][2];
#pragma unroll
        for (int nb = 0; nb < 4; ++nb) {
            const uint32_t boff =
                (uint32_t)(((ks + (c.grp & 1) * 8 + (c.lane & 7)) * BSS +
                            c.wn + nb * 16 + (c.grp >> 1) * 8) * 2);
            uint32_t rh[4], rl[4];
            ldsm_x4t(rh, sBh + boff);
            ldsm_x4t(rl, sBl + boff);
            bh[2 * nb][0] = rh[0]; bh[2 * nb][1] = rh[1];
            bh[2 * nb + 1][0] = rh[2]; bh[2 * nb + 1][1] = rh[3];
            bl[2 * nb][0] = rl[0]; bl[2 * nb][1] = rl[1];
            bl[2 * nb + 1][0] = rl[2]; bl[2 * nb + 1][1] = rl[3];
        }
#pragma unroll
        for (int mi = 0; mi < 2; ++mi)
#pragma unroll
            for (int nj = 0; nj < 8; ++nj)
                mma_bf16(acc[mi][nj], ah[mi], bh[nj][0], bh[nj][1]);
#pragma unroll
        for (int mi = 0; mi < 2; ++mi)
#pragma unroll
            for (int nj = 0; nj < 8; ++nj)
                mma_bf16(acc[mi][nj], ah[mi], bl[nj][0], bl[nj][1]);
#pragma unroll
        for (int mi = 0; mi < 2; ++mi)
#pragma unroll
            for (int nj = 0; nj < 8; ++nj)
                mma_bf16(acc[mi][nj], al[mi], bh[nj][0], bh[nj][1]);
    }
}

// ---------------------------------------------------------------------------
// QKV projection, presplit A (X) and B (Wt [d][h*64+k]); hi/lo bf16 output.
// ---------------------------------------------------------------------------
__global__ __launch_bounds__(256) void proj_ps(const __nv_bfloat16* __restrict__ Xh,
                                               const __nv_bfloat16* __restrict__ Xl,
                                               const __nv_bfloat16* __restrict__ Wh,
                                               const __nv_bfloat16* __restrict__ Wl,
                                               __nv_bfloat16* __restrict__ oh,
                                               __nv_bfloat16* __restrict__ ol) {
    __shared__ __nv_bfloat16 Ah[128 * AS], Al[128 * AS];
    __shared__ __nv_bfloat16 Bh[32 * BSS], Bl[32 * BSS];
    const uint32_t sAh = smem_u32(Ah), sAl = smem_u32(Al);
    const uint32_t sBh = smem_u32(Bh), sBl = smem_u32(Bl);

    const int tid = threadIdx.x;
    const int wid = tid >> 5, lane = tid & 31;
    MmaCtx c{(wid >> 1) * 32, (wid & 1) * 64, lane & 15, lane >> 3, lane};
    const int r0 = lane >> 2, c2 = (lane & 3) * 2;
    const int row0 = blockIdx.x * 128, c0 = blockIdx.y * 128;

    float acc[2][8][4] = {};
    uint4 ar[2][2], br[2][2];

    auto load_regs = [&](int kk) {
#pragma unroll
        for (int rep = 0; rep < 2; ++rep) {
            int idx = tid + rep * 256;
            int r = idx >> 2, kc = (idx & 3) * 8;
            ar[rep][0] = *(const uint4*)(Xh + (size_t)(row0 + r) * Dn + kk + kc);
            ar[rep][1] = *(const uint4*)(Xl + (size_t)(row0 + r) * Dn + kk + kc);
        }
#pragma unroll
        for (int rep = 0; rep < 2; ++rep) {
            int idx = tid + rep * 256;
            int k = idx >> 4, col = (idx & 15) * 8;
            br[rep][0] = *(const uint4*)(Wh + (size_t)(kk + k) * Dn + c0 + col);
            br[rep][1] = *(const uint4*)(Wl + (size_t)(kk + k) * Dn + c0 + col);
        }
    };

    load_regs(0);
    for (int kk = 0; kk < Dn; kk += 32) {
#pragma unroll
        for (int rep = 0; rep < 2; ++rep) {
            int idx = tid + rep * 256;
            int r = idx >> 2, kc = (idx & 3) * 8;
            *(uint4*)&Ah[r * AS + kc] = ar[rep][0];
            *(uint4*)&Al[r * AS + kc] = ar[rep][1];
        }
#pragma unroll
        for (int rep = 0; rep < 2; ++rep) {
            int idx = tid + rep * 256;
            int k = idx >> 4, col = (idx & 15) * 8;
            *(uint4*)&Bh[k * BSS + col] = br[rep][0];
            *(uint4*)&Bl[k * BSS + col] = br[rep][1];
        }
        __syncthreads();
        if (kk + 32 < Dn) load_regs(kk + 32);
        mma_kblock(acc, sAh, sAl, sBh, sBl, c);
        __syncthreads();
    }

#pragma unroll
    for (int mi = 0; mi < 2; ++mi)
#pragma unroll
        for (int rr = 0; rr < 2; ++rr) {
            int row = row0 + c.wm + mi * 16 + r0 + rr * 8;
            int b = row >> 11, s = row & 2047;
#pragma unroll
            for (int nj = 0; nj < 8; ++nj) {
                int colg = c0 + c.wn + nj * 8 + c2;
                int h = colg >> 6, k0 = colg & 63;
                size_t off = (((size_t)(b * Hn + h) * Sn + s) * Kn) + k0;
                uint32_t hv, lv;
                split2(acc[mi][nj][2 * rr], acc[mi][nj][2 * rr + 1], hv, lv);
                *(uint32_t*)(oh + off) = hv;
                *(uint32_t*)(ol + off) = lv;
            }
        }
}

// ---------------------------------------------------------------------------
// Output projection, presplit A (attn out) and B (Wo); fp32 output.
// ---------------------------------------------------------------------------
__global__ __launch_bounds__(256) void outproj_ps(const __nv_bfloat16* __restrict__ Xh,
                                                  const __nv_bfloat16* __restrict__ Xl,
                                                  const __nv_bfloat16* __restrict__ Wh,
                                                  const __nv_bfloat16* __restrict__ Wl,
                                                  float* __restrict__ out) {
    __shared__ __nv_bfloat16 Ah[128 * AS], Al[128 * AS];
    __shared__ __nv_bfloat16 Bh[32 * BSS], Bl[32 * BSS];
    const uint32_t sAh = smem_u32(Ah), sAl = smem_u32(Al);
    const uint32_t sBh = smem_u32(Bh), sBl = smem_u32(Bl);

    const int tid = threadIdx.x;
    const int wid = tid >> 5, lane = tid & 31;
    MmaCtx c{(wid >> 1) * 32, (wid & 1) * 64, lane & 15, lane >> 3, lane};
    const int r0 = lane >> 2, c2 = (lane & 3) * 2;
    const int row0 = blockIdx.x * 128, c0 = blockIdx.y * 128;

    float acc[2][8][4] = {};
    uint4 ar[2][2], br[2][2];

    auto load_regs = [&](int kk) {
#pragma unroll
        for (int rep = 0; rep < 2; ++rep) {
            int idx = tid + rep * 256;
            int r = idx >> 2, kc = (idx & 3) * 8;
            ar[rep][0] = *(const uint4*)(Xh + (size_t)(row0 + r) * Dn + kk + kc);
            ar[rep][1] = *(const uint4*)(Xl + (size_t)(row0 + r) * Dn + kk + kc);
        }
#pragma unroll
        for (int rep = 0; rep < 2; ++rep) {
            int idx = tid + rep * 256;
            int k = idx >> 4, col = (idx & 15) * 8;
            br[rep][0] = *(const uint4*)(Wh + (size_t)(kk + k) * Dn + c0 + col);
            br[rep][1] = *(const uint4*)(Wl + (size_t)(kk + k) * Dn + c0 + col);
        }
    };

    load_regs(0);
    for (int kk = 0; kk < Dn; kk += 32) {
#pragma unroll
        for (int rep = 0; rep < 2; ++rep) {
            int idx = tid + rep * 256;
            int r = idx >> 2, kc = (idx & 3) * 8;
            *(uint4*)&Ah[r * AS + kc] = ar[rep][0];
            *(uint4*)&Al[r * AS + kc] = ar[rep][1];
        }
#pragma unroll
        for (int rep = 0; rep < 2; ++rep) {
            int idx = tid + rep * 256;
            int k = idx >> 4, col = (idx & 15) * 8;
            *(uint4*)&Bh[k * BSS + col] = br[rep][0];
            *(uint4*)&Bl[k * BSS + col] = br[rep][1];
        }
        __syncthreads();
        if (kk + 32 < Dn) load_regs(kk + 32);
        mma_kblock(acc, sAh, sAl, sBh, sBl, c);
        __syncthreads();
    }

#pragma unroll
    for (int mi = 0; mi < 2; ++mi)
#pragma unroll
        for (int rr = 0; rr < 2; ++rr) {
            int row = row0 + c.wm + mi * 16 + r0 + rr * 8;
#pragma unroll
            for (int nj = 0; nj < 8; ++nj) {
                int colg = c0 + c.wn + nj * 8 + c2;
                *(float2*)(out + (size_t)row * Dn + colg) =
                    make_float2(acc[mi][nj][2 * rr], acc[mi][nj][2 * rr + 1]);
            }
        }
}

// ---------------------------------------------------------------------------
extern "C" void kernel_launch(void* const* d_in, const int* in_sizes, int n_in,
                              void* d_out, int out_size) {
    const float* queries = (const float*)d_in[0];
    const float* keys    = (const float*)d_in[1];
    const float* values  = (const float*)d_in[2];
    const float* mask    = (const float*)d_in[3];
    const float* W_q     = (const float*)d_in[4];
    const float* W_k     = (const float*)d_in[5];
    const float* W_v     = (const float*)d_in[6];
    const float* W_o     = (const float*)d_in[7];
    float* out = (float*)d_out;

    __nv_bfloat16 *qh, *ql, *kh, *kl, *vh, *vl, *oh, *ol, *xsh, *xsl, *wsh, *wsl;
    cudaGetSymbolAddress((void**)&qh, g_qh);
    cudaGetSymbolAddress((void**)&ql, g_ql);
    cudaGetSymbolAddress((void**)&kh, g_kh);
    cudaGetSymbolAddress((void**)&kl, g_kl);
    cudaGetSymbolAddress((void**)&vh, g_vh);
    cudaGetSymbolAddress((void**)&vl, g_vl);
    cudaGetSymbolAddress((void**)&oh, g_oh);
    cudaGetSymbolAddress((void**)&ol, g_ol);
    cudaGetSymbolAddress((void**)&xsh, g_xsh);
    cudaGetSymbolAddress((void**)&xsl, g_xsl);
    cudaGetSymbolAddress((void**)&wsh, g_wsh);
    cudaGetSymbolAddress((void**)&wsl, g_wsl);

    cudaFuncSetAttribute(attn_kernel, cudaFuncAttributeMaxDynamicSharedMemorySize, ATTN_SMEM);

    const int nX4 = Bn * Sn * Dn / 4;       // 1572864
    const int nW2 = Dn * (Dn / 2);          // 294912
    const int nWo4 = Dn * Dn / 4;           // 147456
    dim3 gproj(Bn * Sn / 128, Dn / 128);    // (64, 6)

    // Q
    split_flat<<<(nX4 + 255) / 256, 256>>>(queries, xsh, xsl, nX4);
    split_wqkv<<<(nW2 + 255) / 256, 256>>>(W_q, wsh, wsl);
    proj_ps<<<gproj, 256>>>(xsh, xsl, wsh, wsl, qh, ql);
    // K
    split_flat<<<(nX4 + 255) / 256, 256>>>(keys, xsh, xsl, nX4);
    split_wqkv<<<(nW2 + 255) / 256, 256>>>(W_k, wsh, wsl);
    proj_ps<<<gproj, 256>>>(xsh, xsl, wsh, wsl, kh, kl);
    // V
    split_flat<<<(nX4 + 255) / 256, 256>>>(values, xsh, xsl, nX4);
    split_wqkv<<<(nW2 + 255) / 256, 256>>>(W_v, wsh, wsl);
    proj_ps<<<gproj, 256>>>(xsh, xsl, wsh, wsl, vh, vl);

    dim3 gattn(Sn / 128, Hn, Bn);  // (16, 12, 4)
    attn_kernel<<<gattn, 256, ATTN_SMEM>>>(mask);

    split_flat<<<(nWo4 + 255) / 256, 256>>>(W_o, wsh, wsl, nWo4);
    outproj_ps<<<gproj, 256>>>(oh, ol, wsh, wsl, out);
}

// round 11
// speedup vs baseline: 1.0315x; 1.0315x over previous
#include <cuda_runtime.h>
#include <cuda_bf16.h>
#include <cstdint>

#define Bn 4
#define Sn 2048
#define Dn 768
#define Hn 12
#define Kn 64
#define NELEM (Bn * Hn * Sn * Kn)

// Scratch device globals (no cudaMalloc allowed).
__device__ __nv_bfloat16 g_qh[NELEM], g_ql[NELEM];
__device__ __nv_bfloat16 g_kh[NELEM], g_kl[NELEM];
__device__ __nv_bfloat16 g_vh[NELEM], g_vl[NELEM];
__device__ __nv_bfloat16 g_oh[NELEM], g_ol[NELEM];
__device__ float g_bias[Sn * Sn];   // fragment-ordered (1-m)*-1e9*log2e

// ---------------------------------------------------------------------------
// helpers
// ---------------------------------------------------------------------------
__device__ __forceinline__ uint32_t smem_u32(const void* p) {
    uint32_t a;
    asm("{ .reg .u64 t; cvta.to.shared.u64 t, %1; cvt.u32.u64 %0, t; }" : "=r"(a) : "l"(p));
    return a;
}
__device__ __forceinline__ void ldsm_x4(uint32_t (&r)[4], uint32_t addr) {
    asm volatile("ldmatrix.sync.aligned.m8n8.x4.shared.b16 {%0,%1,%2,%3}, [%4];"
                 : "=r"(r[0]), "=r"(r[1]), "=r"(r[2]), "=r"(r[3]) : "r"(addr));
}
__device__ __forceinline__ void ldsm_x4t(uint32_t (&r)[4], uint32_t addr) {
    asm volatile("ldmatrix.sync.aligned.m8n8.x4.trans.shared.b16 {%0,%1,%2,%3}, [%4];"
                 : "=r"(r[0]), "=r"(r[1]), "=r"(r[2]), "=r"(r[3]) : "r"(addr));
}
__device__ __forceinline__ void mma_bf16(float (&d)[4], const uint32_t (&a)[4],
                                         const uint32_t b0, const uint32_t b1) {
    asm volatile(
        "mma.sync.aligned.m16n8k16.row.col.f32.bf16.bf16.f32 "
        "{%0,%1,%2,%3}, {%4,%5,%6,%7}, {%8,%9}, {%0,%1,%2,%3};"
        : "+f"(d[0]), "+f"(d[1]), "+f"(d[2]), "+f"(d[3])
        : "r"(a[0]), "r"(a[1]), "r"(a[2]), "r"(a[3]), "r"(b0), "r"(b1));
}
// packed hi/lo bf16 split: h = {bf16(x), bf16(y)}, l = residuals
__device__ __forceinline__ void split2(float x, float y, uint32_t& h, uint32_t& l) {
    uint32_t hp;
    asm("cvt.rn.bf16x2.f32 %0, %1, %2;" : "=r"(hp) : "f"(y), "f"(x));
    float hx = __uint_as_float(hp << 16);
    float hy = __uint_as_float(hp & 0xFFFF0000u);
    asm("cvt.rn.bf16x2.f32 %0, %1, %2;" : "=r"(l) : "f"(y - hy), "f"(x - hx));
    h = hp;
}
__device__ __forceinline__ float ex2(float x) {
    float y;
    asm("ex2.approx.f32 %0, %1;" : "=f"(y) : "f"(x));
    return y;
}
__device__ __forceinline__ void cpa16(uint32_t dst, const void* src) {
    asm volatile("cp.async.cg.shared.global [%0], [%1], 16;" :: "r"(dst), "l"(src) : "memory");
}
__device__ __forceinline__ void cp_commit() { asm volatile("cp.async.commit_group;" ::: "memory"); }
__device__ __forceinline__ void cp_wait1() { asm volatile("cp.async.wait_group 1;" ::: "memory"); }

#define C_L2E 0.18033688011112042f   // 0.125 * log2(e)

// ---------------------------------------------------------------------------
// Fragment-ordered bias precompute: bias2 = (1-mask)*(-1e9)*log2e, laid out as
// [qt][kt][wid][lane][n][j] matching the attn kernel's per-thread access.
// ---------------------------------------------------------------------------
__global__ void make_bias(const float* __restrict__ mask, float* __restrict__ bias) {
    int i = blockIdx.x * 256 + threadIdx.x;
    if (i >= Sn * Sn) return;
    int j = i & 3, n = (i >> 2) & 7;
    int lane = (i >> 5) & 31, wid = (i >> 10) & 15;
    int kt = (i >> 14) & 15, qt = i >> 18;
    int qw = wid >> 1, half = wid & 1;
    int q = qt * 128 + qw * 16 + (lane >> 2) + ((j >> 1) << 3);
    int col = kt * 128 + half * 64 + n * 8 + (lane & 3) * 2 + (j & 1);
    bias[i] = (1.f - mask[(size_t)q * Sn + col]) * (-1e9f) * 1.4426950408889634f;
}

// ===========================================================================
// Attention: 512 threads / 16 warps. Warp (qw, half): qw = wid>>1 owns q rows
// [16qw,16qw+16), half = wid&1 owns S cols / kv rows [64*half, 64*half+64).
// K/V tiles double-buffered via cp.async. No-max softmax (ex2 + folded bias).
// ===========================================================================
#define QS 72
#define TILE_E (128 * QS)
#define SM_MAXB (10 * TILE_E * 2)      // byte offset of l buffer
#define ATTN_SMEM (SM_MAXB + 256 * 4)

__global__ __launch_bounds__(512, 1) void attn_kernel() {
    extern __shared__ __nv_bfloat16 smbf[];
    const uint32_t smb = smem_u32(smbf);
    const uint32_t sQh = smb, sQl = smb + TILE_E * 2;
    float* mbuf = (float*)((char*)smbf + SM_MAXB);
    float* Obuf = (float*)(smbf + 2 * TILE_E);  // reuses stage0 region post-loop

    const int tid = threadIdx.x;
    const int wid = tid >> 5, lane = tid & 31;
    const int qw = wid >> 1, half = wid & 1;
    const int cb = half * 64;
    const int l16 = lane & 15;
    const int g = lane >> 3;
    const int r0 = lane >> 2;
    const int c2 = (lane & 3) * 2;
    const int qt = blockIdx.x, hd = blockIdx.y, b = blockIdx.z;
    const size_t bh = (size_t)(b * Hn + hd) * Sn;
    const int qr0 = qw * 16;

    const int ld_r = tid >> 3, ld_c = (tid & 7) * 8;
    const int ld_r1 = (tid + 512) >> 3;

    // Q tile hi/lo, plain loads (once).
    {
        const __nv_bfloat16* qh = g_qh + (bh + (size_t)qt * 128) * Kn;
        const __nv_bfloat16* ql = g_ql + (bh + (size_t)qt * 128) * Kn;
#pragma unroll
        for (int rep = 0; rep < 2; ++rep) {
            int r = rep ? ld_r1 : ld_r;
            *(uint4*)(smbf + r * QS + ld_c) = *(const uint4*)(qh + r * 64 + ld_c);
            *(uint4*)(smbf + TILE_E + r * QS + ld_c) = *(const uint4*)(ql + r * 64 + ld_c);
        }
    }

    auto issue_tile = [&](int kt2, int st) {
        const __nv_bfloat16* kh = g_kh + (bh + (size_t)kt2 * 128) * Kn;
        const __nv_bfloat16* kl = g_kl + (bh + (size_t)kt2 * 128) * Kn;
        const __nv_bfloat16* vh = g_vh + (bh + (size_t)kt2 * 128) * Kn;
        const __nv_bfloat16* vl = g_vl + (bh + (size_t)kt2 * 128) * Kn;
        const uint32_t base = smb + (uint32_t)(2 + st * 4) * (TILE_E * 2);
#pragma unroll
        for (int rep = 0; rep < 2; ++rep) {
            int r = rep ? ld_r1 : ld_r;
            uint32_t off = (uint32_t)(r * QS + ld_c) * 2;
            cpa16(base + off, kh + r * 64 + ld_c);
            cpa16(base + TILE_E * 2 + off, kl + r * 64 + ld_c);
            cpa16(base + TILE_E * 4 + off, vh + r * 64 + ld_c);
            cpa16(base + TILE_E * 6 + off, vl + r * 64 + ld_c);
        }
    };

    issue_tile(0, 0);
    cp_commit();
    issue_tile(1, 1);
    cp_commit();

    float oacc[8][4];
#pragma unroll
    for (int n = 0; n < 8; ++n)
#pragma unroll
        for (int j = 0; j < 4; ++j) oacc[n][j] = 0.f;
    float lh0 = 0.f, lh1 = 0.f;

    // fragment-ordered bias base for this thread (advance by 16*32*32 per kt)
    const float4* bp = (const float4*)(g_bias + ((((size_t)qt * 16) * 16 + wid) * 32 + lane) * 32);
    const int bstride = 16 * 32 * 32 / 4;   // float4 stride per kt

    for (int kt = 0; kt < Sn / 128; ++kt) {
        const int st = kt & 1;
        const uint32_t sKh = smb + (uint32_t)(2 + st * 4) * (TILE_E * 2);
        const uint32_t sKl = sKh + TILE_E * 2;
        const uint32_t sVh = sKh + TILE_E * 4;
        const uint32_t sVl = sKh + TILE_E * 6;

        cp_wait1();
        __syncthreads();

        // ---- S = Q @ K^T: fragments first, then term-grouped MMAs ----
        float sacc[8][4];
#pragma unroll
        for (int n = 0; n < 8; ++n)
#pragma unroll
            for (int j = 0; j < 4; ++j) sacc[n][j] = 0.f;

#pragma unroll
        for (int ks = 0; ks < 4; ++ks) {
            uint32_t aqh[4], aql[4];
            const uint32_t aoff =
                (uint32_t)(((qr0 + l16) * QS + ks * 16 + (lane >> 4) * 8) * 2);
            ldsm_x4(aqh, sQh + aoff);
            ldsm_x4(aql, sQl + aoff);
            uint32_t rh[4][4], rl[4][4];
#pragma unroll
            for (int n2 = 0; n2 < 4; ++n2) {
                const uint32_t boff =
                    (uint32_t)(((cb + n2 * 16 + (g >> 1) * 8 + (lane & 7)) * QS +
                                ks * 16 + (g & 1) * 8) * 2);
                ldsm_x4(rh[n2], sKh + boff);
                ldsm_x4(rl[n2], sKl + boff);
            }
#pragma unroll
            for (int n2 = 0; n2 < 4; ++n2) {
                mma_bf16(sacc[2 * n2], aqh, rh[n2][0], rh[n2][1]);
                mma_bf16(sacc[2 * n2 + 1], aqh, rh[n2][2], rh[n2][3]);
            }
#pragma unroll
            for (int n2 = 0; n2 < 4; ++n2) {
                mma_bf16(sacc[2 * n2], aqh, rl[n2][0], rl[n2][1]);
                mma_bf16(sacc[2 * n2 + 1], aqh, rl[n2][2], rl[n2][3]);
            }
#pragma unroll
            for (int n2 = 0; n2 < 4; ++n2) {
                mma_bf16(sacc[2 * n2], aql, rh[n2][0], rh[n2][1]);
                mma_bf16(sacc[2 * n2 + 1], aql, rh[n2][2], rh[n2][3]);
            }
        }

        // ---- scale + bias + exp2 (no max subtraction) ----
        const float4* bpk = bp + (size_t)kt * bstride;
#pragma unroll
        for (int n = 0; n < 8; ++n) {
            float4 bb = __ldg(bpk + n);
            sacc[n][0] = ex2(fmaf(sacc[n][0], C_L2E, bb.x));
            sacc[n][1] = ex2(fmaf(sacc[n][1], C_L2E, bb.y));
            sacc[n][2] = ex2(fmaf(sacc[n][2], C_L2E, bb.z));
            sacc[n][3] = ex2(fmaf(sacc[n][3], C_L2E, bb.w));
            lh0 += sacc[n][0] + sacc[n][1];
            lh1 += sacc[n][2] + sacc[n][3];
        }

        // ---- O_half += P @ V_half: fragments + splits first, term-grouped ----
#pragma unroll
        for (int j = 0; j < 4; ++j) {
            uint32_t ah[4], al[4];
            split2(sacc[2 * j][0], sacc[2 * j][1], ah[0], al[0]);
            split2(sacc[2 * j][2], sacc[2 * j][3], ah[1], al[1]);
            split2(sacc[2 * j + 1][0], sacc[2 * j + 1][1], ah[2], al[2]);
            split2(sacc[2 * j + 1][2], sacc[2 * j + 1][3], ah[3], al[3]);
            uint32_t rh[4][4], rl[4][4];
#pragma unroll
            for (int nv2 = 0; nv2 < 4; ++nv2) {
                const uint32_t voff =
                    (uint32_t)(((cb + j * 16 + (g & 1) * 8 + (lane & 7)) * QS +
                                nv2 * 16 + (g >> 1) * 8) * 2);
                ldsm_x4t(rh[nv2], sVh + voff);
                ldsm_x4t(rl[nv2], sVl + voff);
            }
#pragma unroll
            for (int nv2 = 0; nv2 < 4; ++nv2) {
                mma_bf16(oacc[2 * nv2], ah, rh[nv2][0], rh[nv2][1]);
                mma_bf16(oacc[2 * nv2 + 1], ah, rh[nv2][2], rh[nv2][3]);
            }
#pragma unroll
            for (int nv2 = 0; nv2 < 4; ++nv2) {
                mma_bf16(oacc[2 * nv2], ah, rl[nv2][0], rl[nv2][1]);
                mma_bf16(oacc[2 * nv2 + 1], ah, rl[nv2][2], rl[nv2][3]);
            }
#pragma unroll
            for (int nv2 = 0; nv2 < 4; ++nv2) {
                mma_bf16(oacc[2 * nv2], al, rh[nv2][0], rh[nv2][1]);
                mma_bf16(oacc[2 * nv2 + 1], al, rh[nv2][2], rh[nv2][3]);
            }
        }

        __syncthreads();  // stage st fully consumed
        if (kt + 2 < Sn / 128) issue_tile(kt + 2, st);
        cp_commit();
    }

    // ---- final l reduction (once), merge halves, normalize, store ----
#pragma unroll
    for (int w = 1; w < 4; w <<= 1) {
        lh0 += __shfl_xor_sync(0xffffffffu, lh0, w);
        lh1 += __shfl_xor_sync(0xffffffffu, lh1, w);
    }
    {
        float* Ow = Obuf + (size_t)half * 128 * 64;
#pragma unroll
        for (int nv = 0; nv < 8; ++nv) {
            *(float2*)(Ow + (qr0 + r0) * 64 + nv * 8 + c2) =
                make_float2(oacc[nv][0], oacc[nv][1]);
            *(float2*)(Ow + (qr0 + r0 + 8) * 64 + nv * 8 + c2) =
                make_float2(oacc[nv][2], oacc[nv][3]);
        }
        if ((lane & 3) == 0) {
            mbuf[(qr0 + r0) * 2 + half] = lh0;
            mbuf[(qr0 + r0 + 8) * 2 + half] = lh1;
        }
    }
    __syncthreads();
#pragma unroll
    for (int rep = 0; rep < 8; ++rep) {
        int idx = tid + rep * 512;
        int r = idx >> 5, cc = (idx & 31) * 2;
        float2 a = *(float2*)(Obuf + r * 64 + cc);
        float2 bb = *(float2*)(Obuf + (128 + r) * 64 + cc);
        float inv = 1.f / (mbuf[r * 2] + mbuf[r * 2 + 1]);
        uint32_t hv, lv;
        split2((a.x + bb.x) * inv, (a.y + bb.y) * inv, hv, lv);
        size_t off = (bh + (size_t)(qt * 128 + r)) * Kn + cc;
        *(uint32_t*)(g_oh + off) = hv;
        *(uint32_t*)(g_ol + off) = lv;
    }
}

// ===========================================================================
// mma.sync GEMM core: C[128 x 128] tile, BK=32, 8 warps (m32 x n64 each).
// ===========================================================================
#define AS 40
#define BSS 136

struct MmaCtx {
    int wm, wn, l16, grp, lane;
};

__device__ __forceinline__ void mma_kblock(float (&acc)[2][8][4],
                                           uint32_t sAh, uint32_t sAl,
                                           uint32_t sBh, uint32_t sBl,
                                           const MmaCtx& c) {
#pragma unroll
    for (int ks = 0; ks < 32; ks += 16) {
        uint32_t ah[2][4], al[2][4];
#pragma unroll
        for (int mi = 0; mi < 2; ++mi) {
            const uint32_t aoff =
                (uint32_t)(((c.wm + mi * 16 + c.l16) * AS + ks + (c.lane >> 4) * 8) * 2);
            ldsm_x4(ah[mi], sAh + aoff);
            ldsm_x4(al[mi], sAl + aoff);
        }
        uint32_t bh[8][2], bl[8][2];
#pragma unroll
        for (int nb = 0; nb < 4; ++nb) {
            const uint32_t boff =
                (uint32_t)(((ks + (c.grp & 1) * 8 + (c.lane & 7)) * BSS +
                            c.wn + nb * 16 + (c.grp >> 1) * 8) * 2);
            uint32_t rh[4], rl[4];
            ldsm_x4t(rh, sBh + boff);
            ldsm_x4t(rl, sBl + boff);
            bh[2 * nb][0] = rh[0]; bh[2 * nb][1] = rh[1];
            bh[2 * nb + 1][0] = rh[2]; bh[2 * nb + 1][1] = rh[3];
            bl[2 * nb][0] = rl[0]; bl[2 * nb][1] = rl[1];
            bl[2 * nb + 1][0] = rl[2]; bl[2 * nb + 1][1] = rl[3];
        }
#pragma unroll
        for (int mi = 0; mi < 2; ++mi)
#pragma unroll
            for (int nj = 0; nj < 8; ++nj)
                mma_bf16(acc[mi][nj], ah[mi], bh[nj][0], bh[nj][1]);
#pragma unroll
        for (int mi = 0; mi < 2; ++mi)
#pragma unroll
            for (int nj = 0; nj < 8; ++nj)
                mma_bf16(acc[mi][nj], ah[mi], bl[nj][0], bl[nj][1]);
#pragma unroll
        for (int mi = 0; mi < 2; ++mi)
#pragma unroll
            for (int nj = 0; nj < 8; ++nj)
                mma_bf16(acc[mi][nj], al[mi], bh[nj][0], bh[nj][1]);
    }
}

// ---------------------------------------------------------------------------
// QKV projection (tensor cores) with register prefetch of the next k-slice.
// ---------------------------------------------------------------------------
__global__ __launch_bounds__(256) void proj_mma(const float* __restrict__ X,
                                                const float* __restrict__ W,
                                                __nv_bfloat16* __restrict__ oh,
                                                __nv_bfloat16* __restrict__ ol) {
    __shared__ __nv_bfloat16 Ah[128 * AS], Al[128 * AS];
    __shared__ __nv_bfloat16 Bh[32 * BSS], Bl[32 * BSS];
    const uint32_t sAh = smem_u32(Ah), sAl = smem_u32(Al);
    const uint32_t sBh = smem_u32(Bh), sBl = smem_u32(Bl);

    const int tid = threadIdx.x;
    const int wid = tid >> 5, lane = tid & 31;
    MmaCtx c{(wid >> 1) * 32, (wid & 1) * 64, lane & 15, lane >> 3, lane};
    const int r0 = lane >> 2, c2 = (lane & 3) * 2;
    const int row0 = blockIdx.x * 128, c0 = blockIdx.y * 128;

    float acc[2][8][4] = {};
    float4 xr[4];
    float2 wr[8];

    auto load_regs = [&](int kk) {
#pragma unroll
        for (int rep = 0; rep < 4; ++rep) {
            int idx = tid + rep * 256;
            int r = idx >> 3, kc = (idx & 7) * 4;
            xr[rep] = *(const float4*)(X + (size_t)(row0 + r) * Dn + kk + kc);
        }
#pragma unroll
        for (int rep = 0; rep < 8; ++rep) {
            int idx = tid + rep * 256;
            int k = idx >> 6, col = (idx & 63) * 2;
            int colg = c0 + col;
            int h = colg >> 6, kidx = colg & 63;
            wr[rep] = *(const float2*)(W + (size_t)(h * Dn + kk + k) * Kn + kidx);
        }
    };

    load_regs(0);
    for (int kk = 0; kk < Dn; kk += 32) {
#pragma unroll
        for (int rep = 0; rep < 4; ++rep) {
            int idx = tid + rep * 256;
            int r = idx >> 3, kc = (idx & 7) * 4;
            uint32_t h0, l0, h1, l1;
            split2(xr[rep].x, xr[rep].y, h0, l0);
            split2(xr[rep].z, xr[rep].w, h1, l1);
            *(uint2*)&Ah[r * AS + kc] = make_uint2(h0, h1);
            *(uint2*)&Al[r * AS + kc] = make_uint2(l0, l1);
        }
#pragma unroll
        for (int rep = 0; rep < 8; ++rep) {
            int idx = tid + rep * 256;
            int k = idx >> 6, col = (idx & 63) * 2;
            uint32_t bh, bl;
            split2(wr[rep].x, wr[rep].y, bh, bl);
            *(uint32_t*)&Bh[k * BSS + col] = bh;
            *(uint32_t*)&Bl[k * BSS + col] = bl;
        }
        __syncthreads();
        if (kk + 32 < Dn) load_regs(kk + 32);
        mma_kblock(acc, sAh, sAl, sBh, sBl, c);
        __syncthreads();
    }

#pragma unroll
    for (int mi = 0; mi < 2; ++mi)
#pragma unroll
        for (int rr = 0; rr < 2; ++rr) {
            int row = row0 + c.wm + mi * 16 + r0 + rr * 8;
            int b = row >> 11, s = row & 2047;
#pragma unroll
            for (int nj = 0; nj < 8; ++nj) {
                int colg = c0 + c.wn + nj * 8 + c2;
                int h = colg >> 6, k0 = colg & 63;
                size_t off = (((size_t)(b * Hn + h) * Sn + s) * Kn) + k0;
                uint32_t hv, lv;
                split2(acc[mi][nj][2 * rr], acc[mi][nj][2 * rr + 1], hv, lv);
                *(uint32_t*)(oh + off) = hv;
                *(uint32_t*)(ol + off) = lv;
            }
        }
}

// ---------------------------------------------------------------------------
// Output projection (tensor cores); A pre-split bf16; register prefetch.
// ---------------------------------------------------------------------------
__global__ __launch_bounds__(256) void outproj_mma(const __nv_bfloat16* __restrict__ Xh,
                                                   const __nv_bfloat16* __restrict__ Xl,
                                                   const float* __restrict__ Wo,
                                                   float* __restrict__ out) {
    __shared__ __nv_bfloat16 Ah[128 * AS], Al[128 * AS];
    __shared__ __nv_bfloat16 Bh[32 * BSS], Bl[32 * BSS];
    const uint32_t sAh = smem_u32(Ah), sAl = smem_u32(Al);
    const uint32_t sBh = smem_u32(Bh), sBl = smem_u32(Bl);

    const int tid = threadIdx.x;
    const int wid = tid >> 5, lane = tid & 31;
    MmaCtx c{(wid >> 1) * 32, (wid & 1) * 64, lane & 15, lane >> 3, lane};
    const int r0 = lane >> 2, c2 = (lane & 3) * 2;
    const int row0 = blockIdx.x * 128, c0 = blockIdx.y * 128;

    float acc[2][8][4] = {};
    uint4 ar[2][2];
    float2 wr[8];

    auto load_regs = [&](int kk) {
#pragma unroll
        for (int rep = 0; rep < 2; ++rep) {
            int idx = tid + rep * 256;
            int r = idx >> 2, kc = (idx & 3) * 8;
            ar[rep][0] = *(const uint4*)(Xh + (size_t)(row0 + r) * Dn + kk + kc);
            ar[rep][1] = *(const uint4*)(Xl + (size_t)(row0 + r) * Dn + kk + kc);
        }
#pragma unroll
        for (int rep = 0; rep < 8; ++rep) {
            int idx = tid + rep * 256;
            int k = idx >> 6, col = (idx & 63) * 2;
            wr[rep] = *(const float2*)(Wo + (size_t)(kk + k) * Dn + c0 + col);
        }
    };

    load_regs(0);
    for (int kk = 0; kk < Dn; kk += 32) {
#pragma unroll
        for (int rep = 0; rep < 2; ++rep) {
            int idx = tid + rep * 256;
            int r = idx >> 2, kc = (idx & 3) * 8;
            *(uint4*)&Ah[r * AS + kc] = ar[rep][0];
            *(uint4*)&Al[r * AS + kc] = ar[rep][1];
        }
#pragma unroll
        for (int rep = 0; rep < 8; ++rep) {
            int idx = tid + rep * 256;
            int k = idx >> 6, col = (idx & 63) * 2;
            uint32_t bh, bl;
            split2(wr[rep].x, wr[rep].y, bh, bl);
            *(uint32_t*)&Bh[k * BSS + col] = bh;
            *(uint32_t*)&Bl[k * BSS + col] = bl;
        }
        __syncthreads();
        if (kk + 32 < Dn) load_regs(kk + 32);
        mma_kblock(acc, sAh, sAl, sBh, sBl, c);
        __syncthreads();
    }

#pragma unroll
    for (int mi = 0; mi < 2; ++mi)
#pragma unroll
        for (int rr = 0; rr < 2; ++rr) {
            int row = row0 + c.wm + mi * 16 + r0 + rr * 8;
#pragma unroll
            for (int nj = 0; nj < 8; ++nj) {
                int colg = c0 + c.wn + nj * 8 + c2;
                *(float2*)(out + (size_t)row * Dn + colg) =
                    make_float2(acc[mi][nj][2 * rr], acc[mi][nj][2 * rr + 1]);
            }
        }
}

// ---------------------------------------------------------------------------
extern "C" void kernel_launch(void* const* d_in, const int* in_sizes, int n_in,
                              void* d_out, int out_size) {
    const float* queries = (const float*)d_in[0];
    const float* keys    = (const float*)d_in[1];
    const float* values  = (const float*)d_in[2];
    const float* mask    = (const float*)d_in[3];
    const float* W_q     = (const float*)d_in[4];
    const float* W_k     = (const float*)d_in[5];
    const float* W_v     = (const float*)d_in[6];
    const float* W_o     = (const float*)d_in[7];
    float* out = (float*)d_out;

    __nv_bfloat16 *qh, *ql, *kh, *kl, *vh, *vl, *oh, *ol;
    float* bias;
    cudaGetSymbolAddress((void**)&qh, g_qh);
    cudaGetSymbolAddress((void**)&ql, g_ql);
    cudaGetSymbolAddress((void**)&kh, g_kh);
    cudaGetSymbolAddress((void**)&kl, g_kl);
    cudaGetSymbolAddress((void**)&vh, g_vh);
    cudaGetSymbolAddress((void**)&vl, g_vl);
    cudaGetSymbolAddress((void**)&oh, g_oh);
    cudaGetSymbolAddress((void**)&ol, g_ol);
    cudaGetSymbolAddress((void**)&bias, g_bias);

    cudaFuncSetAttribute(attn_kernel, cudaFuncAttributeMaxDynamicSharedMemorySize, ATTN_SMEM);

    make_bias<<<(Sn * Sn + 255) / 256, 256>>>(mask, bias);

    dim3 gproj(Bn * Sn / 128, Dn / 128);  // (64, 6)
    proj_mma<<<gproj, 256>>>(queries, W_q, qh, ql);
    proj_mma<<<gproj, 256>>>(keys,    W_k, kh, kl);
    proj_mma<<<gproj, 256>>>(values,  W_v, vh, vl);

    dim3 gattn(Sn / 128, Hn, Bn);  // (16, 12, 4)
    attn_kernel<<<gattn, 512, ATTN_SMEM>>>();

    dim3 gout(Bn * Sn / 128, Dn / 128);  // (64, 6)
    outproj_mma<<<gout, 256>>>(oh, ol, W_o, out);
}

// round 12
// speedup vs baseline: 1.1458x; 1.1108x over previous
#include <cuda_runtime.h>
#include <cuda_bf16.h>
#include <cstdint>

#define Bn 4
#define Sn 2048
#define Dn 768
#define Hn 12
#define Kn 64
#define NELEM (Bn * Hn * Sn * Kn)

// Scratch device globals (no cudaMalloc allowed).
__device__ __nv_bfloat16 g_qh[NELEM], g_ql[NELEM];
__device__ __nv_bfloat16 g_kh[NELEM], g_kl[NELEM];
__device__ __nv_bfloat16 g_vh[NELEM], g_vl[NELEM];
__device__ __nv_bfloat16 g_oh[NELEM], g_ol[NELEM];

// ---------------------------------------------------------------------------
// helpers (R9-proven versions)
// ---------------------------------------------------------------------------
__device__ __forceinline__ uint32_t smem_u32(const void* p) {
    uint32_t a;
    asm("{ .reg .u64 t; cvta.to.shared.u64 t, %1; cvt.u32.u64 %0, t; }" : "=r"(a) : "l"(p));
    return a;
}
__device__ __forceinline__ void ldsm_x4(uint32_t (&r)[4], uint32_t addr) {
    asm volatile("ldmatrix.sync.aligned.m8n8.x4.shared.b16 {%0,%1,%2,%3}, [%4];"
                 : "=r"(r[0]), "=r"(r[1]), "=r"(r[2]), "=r"(r[3]) : "r"(addr));
}
__device__ __forceinline__ void ldsm_x4t(uint32_t (&r)[4], uint32_t addr) {
    asm volatile("ldmatrix.sync.aligned.m8n8.x4.trans.shared.b16 {%0,%1,%2,%3}, [%4];"
                 : "=r"(r[0]), "=r"(r[1]), "=r"(r[2]), "=r"(r[3]) : "r"(addr));
}
__device__ __forceinline__ void mma_bf16(float (&d)[4], const uint32_t (&a)[4],
                                         const uint32_t b0, const uint32_t b1) {
    asm volatile(
        "mma.sync.aligned.m16n8k16.row.col.f32.bf16.bf16.f32 "
        "{%0,%1,%2,%3}, {%4,%5,%6,%7}, {%8,%9}, {%0,%1,%2,%3};"
        : "+f"(d[0]), "+f"(d[1]), "+f"(d[2]), "+f"(d[3])
        : "r"(a[0]), "r"(a[1]), "r"(a[2]), "r"(a[3]), "r"(b0), "r"(b1));
}
__device__ __forceinline__ void split2(float x, float y, uint32_t& h, uint32_t& l) {
    __nv_bfloat16 hx = __float2bfloat16(x), hy = __float2bfloat16(y);
    __nv_bfloat16 lx = __float2bfloat16(x - __bfloat162float(hx));
    __nv_bfloat16 ly = __float2bfloat16(y - __bfloat162float(hy));
    __nv_bfloat162 hh = __halves2bfloat162(hx, hy);
    __nv_bfloat162 ll = __halves2bfloat162(lx, ly);
    h = *(uint32_t*)&hh;
    l = *(uint32_t*)&ll;
}
__device__ __forceinline__ void cpa16(uint32_t dst, const void* src) {
    asm volatile("cp.async.cg.shared.global [%0], [%1], 16;" :: "r"(dst), "l"(src) : "memory");
}
__device__ __forceinline__ void cp_commit() { asm volatile("cp.async.commit_group;" ::: "memory"); }
__device__ __forceinline__ void cp_wait1() { asm volatile("cp.async.wait_group 1;" ::: "memory"); }

// ===========================================================================
// Attention (exact R9 983us version): 512 threads / 16 warps.
// Warp (qw, half): qw = wid>>1 owns q rows [16qw,16qw+16), half = wid&1 owns
// S cols / kv rows [64half, 64half+64). cp.async double buffer, no-max softmax.
// ===========================================================================
#define QS 72
#define TILE_E (128 * QS)
#define SM_MAXB (10 * TILE_E * 2)
#define ATTN_SMEM (SM_MAXB + 256 * 4)

__global__ __launch_bounds__(512, 1) void attn_kernel(const float* __restrict__ mask) {
    extern __shared__ __nv_bfloat16 smbf[];
    const uint32_t smb = smem_u32(smbf);
    const uint32_t sQh = smb, sQl = smb + TILE_E * 2;
    float* mbuf = (float*)((char*)smbf + SM_MAXB);
    float* Obuf = (float*)(smbf + 2 * TILE_E);

    const int tid = threadIdx.x;
    const int wid = tid >> 5, lane = tid & 31;
    const int qw = wid >> 1, half = wid & 1;
    const int cb = half * 64;
    const int l16 = lane & 15;
    const int g = lane >> 3;
    const int r0 = lane >> 2;
    const int c2 = (lane & 3) * 2;
    const int qt = blockIdx.x, hd = blockIdx.y, b = blockIdx.z;
    const size_t bh = (size_t)(b * Hn + hd) * Sn;
    const int qr0 = qw * 16;
    const int qg0 = qt * 128 + qr0;

    const int ld_r = tid >> 3, ld_c = (tid & 7) * 8;
    const int ld_r1 = (tid + 512) >> 3;

    {
        const __nv_bfloat16* qh = g_qh + (bh + (size_t)qt * 128) * Kn;
        const __nv_bfloat16* ql = g_ql + (bh + (size_t)qt * 128) * Kn;
#pragma unroll
        for (int rep = 0; rep < 2; ++rep) {
            int r = rep ? ld_r1 : ld_r;
            *(uint4*)(smbf + r * QS + ld_c) = *(const uint4*)(qh + r * 64 + ld_c);
            *(uint4*)(smbf + TILE_E + r * QS + ld_c) = *(const uint4*)(ql + r * 64 + ld_c);
        }
    }

    auto issue_tile = [&](int kt2, int st) {
        const __nv_bfloat16* kh = g_kh + (bh + (size_t)kt2 * 128) * Kn;
        const __nv_bfloat16* kl = g_kl + (bh + (size_t)kt2 * 128) * Kn;
        const __nv_bfloat16* vh = g_vh + (bh + (size_t)kt2 * 128) * Kn;
        const __nv_bfloat16* vl = g_vl + (bh + (size_t)kt2 * 128) * Kn;
        const uint32_t base = smb + (uint32_t)(2 + st * 4) * (TILE_E * 2);
#pragma unroll
        for (int rep = 0; rep < 2; ++rep) {
            int r = rep ? ld_r1 : ld_r;
            uint32_t off = (uint32_t)(r * QS + ld_c) * 2;
            cpa16(base + off, kh + r * 64 + ld_c);
            cpa16(base + TILE_E * 2 + off, kl + r * 64 + ld_c);
            cpa16(base + TILE_E * 4 + off, vh + r * 64 + ld_c);
            cpa16(base + TILE_E * 6 + off, vl + r * 64 + ld_c);
        }
    };

    issue_tile(0, 0);
    cp_commit();
    issue_tile(1, 1);
    cp_commit();

    float oacc[8][4];
#pragma unroll
    for (int n = 0; n < 8; ++n)
#pragma unroll
        for (int j = 0; j < 4; ++j) oacc[n][j] = 0.f;
    float lh0 = 0.f, lh1 = 0.f;

    const float* mp0 = mask + (size_t)(qg0 + r0) * Sn;
    const float* mp1 = mp0 + 8 * Sn;
    const float scale = 0.125f;

    for (int kt = 0; kt < Sn / 128; ++kt) {
        const int st = kt & 1;
        const uint32_t sKh = smb + (uint32_t)(2 + st * 4) * (TILE_E * 2);
        const uint32_t sKl = sKh + TILE_E * 2;
        const uint32_t sVh = sKh + TILE_E * 4;
        const uint32_t sVl = sKh + TILE_E * 6;

        cp_wait1();
        __syncthreads();

        float sacc[8][4];
#pragma unroll
        for (int n = 0; n < 8; ++n)
#pragma unroll
            for (int j = 0; j < 4; ++j) sacc[n][j] = 0.f;

#pragma unroll
        for (int ks = 0; ks < 4; ++ks) {
            uint32_t aqh[4], aql[4];
            const uint32_t aoff =
                (uint32_t)(((qr0 + l16) * QS + ks * 16 + (lane >> 4) * 8) * 2);
            ldsm_x4(aqh, sQh + aoff);
            ldsm_x4(aql, sQl + aoff);
            uint32_t rh[4][4], rl[4][4];
#pragma unroll
            for (int n2 = 0; n2 < 4; ++n2) {
                const uint32_t boff =
                    (uint32_t)(((cb + n2 * 16 + (g >> 1) * 8 + (lane & 7)) * QS +
                                ks * 16 + (g & 1) * 8) * 2);
                ldsm_x4(rh[n2], sKh + boff);
                ldsm_x4(rl[n2], sKl + boff);
            }
#pragma unroll
            for (int n2 = 0; n2 < 4; ++n2) {
                mma_bf16(sacc[2 * n2], aqh, rh[n2][0], rh[n2][1]);
                mma_bf16(sacc[2 * n2 + 1], aqh, rh[n2][2], rh[n2][3]);
            }
#pragma unroll
            for (int n2 = 0; n2 < 4; ++n2) {
                mma_bf16(sacc[2 * n2], aqh, rl[n2][0], rl[n2][1]);
                mma_bf16(sacc[2 * n2 + 1], aqh, rl[n2][2], rl[n2][3]);
            }
#pragma unroll
            for (int n2 = 0; n2 < 4; ++n2) {
                mma_bf16(sacc[2 * n2], aql, rh[n2][0], rh[n2][1]);
                mma_bf16(sacc[2 * n2 + 1], aql, rh[n2][2], rh[n2][3]);
            }
        }

#pragma unroll
        for (int n = 0; n < 8; ++n) {
            const int col = kt * 128 + cb + n * 8 + c2;
            float2 mv0 = __ldg((const float2*)(mp0 + col));
            float2 mv1 = __ldg((const float2*)(mp1 + col));
            sacc[n][0] = __expf(fmaf(sacc[n][0], scale, (1.f - mv0.x) * -1e9f));
            sacc[n][1] = __expf(fmaf(sacc[n][1], scale, (1.f - mv0.y) * -1e9f));
            sacc[n][2] = __expf(fmaf(sacc[n][2], scale, (1.f - mv1.x) * -1e9f));
            sacc[n][3] = __expf(fmaf(sacc[n][3], scale, (1.f - mv1.y) * -1e9f));
            lh0 += sacc[n][0] + sacc[n][1];
            lh1 += sacc[n][2] + sacc[n][3];
        }

#pragma unroll
        for (int j = 0; j < 4; ++j) {
            uint32_t ah[4], al[4];
            split2(sacc[2 * j][0], sacc[2 * j][1], ah[0], al[0]);
            split2(sacc[2 * j][2], sacc[2 * j][3], ah[1], al[1]);
            split2(sacc[2 * j + 1][0], sacc[2 * j + 1][1], ah[2], al[2]);
            split2(sacc[2 * j + 1][2], sacc[2 * j + 1][3], ah[3], al[3]);
            uint32_t rh[4][4], rl[4][4];
#pragma unroll
            for (int nv2 = 0; nv2 < 4; ++nv2) {
                const uint32_t voff =
                    (uint32_t)(((cb + j * 16 + (g & 1) * 8 + (lane & 7)) * QS +
                                nv2 * 16 + (g >> 1) * 8) * 2);
                ldsm_x4t(rh[nv2], sVh + voff);
                ldsm_x4t(rl[nv2], sVl + voff);
            }
#pragma unroll
            for (int nv2 = 0; nv2 < 4; ++nv2) {
                mma_bf16(oacc[2 * nv2], ah, rh[nv2][0], rh[nv2][1]);
                mma_bf16(oacc[2 * nv2 + 1], ah, rh[nv2][2], rh[nv2][3]);
            }
#pragma unroll
            for (int nv2 = 0; nv2 < 4; ++nv2) {
                mma_bf16(oacc[2 * nv2], ah, rl[nv2][0], rl[nv2][1]);
                mma_bf16(oacc[2 * nv2 + 1], ah, rl[nv2][2], rl[nv2][3]);
            }
#pragma unroll
            for (int nv2 = 0; nv2 < 4; ++nv2) {
                mma_bf16(oacc[2 * nv2], al, rh[nv2][0], rh[nv2][1]);
                mma_bf16(oacc[2 * nv2 + 1], al, rh[nv2][2], rh[nv2][3]);
            }
        }

        __syncthreads();
        if (kt + 2 < Sn / 128) issue_tile(kt + 2, st);
        cp_commit();
    }

#pragma unroll
    for (int w = 1; w < 4; w <<= 1) {
        lh0 += __shfl_xor_sync(0xffffffffu, lh0, w);
        lh1 += __shfl_xor_sync(0xffffffffu, lh1, w);
    }
    {
        float* Ow = Obuf + (size_t)half * 128 * 64;
#pragma unroll
        for (int nv = 0; nv < 8; ++nv) {
            *(float2*)(Ow + (qr0 + r0) * 64 + nv * 8 + c2) =
                make_float2(oacc[nv][0], oacc[nv][1]);
            *(float2*)(Ow + (qr0 + r0 + 8) * 64 + nv * 8 + c2) =
                make_float2(oacc[nv][2], oacc[nv][3]);
        }
        if ((lane & 3) == 0) {
            mbuf[(qr0 + r0) * 2 + half] = lh0;
            mbuf[(qr0 + r0 + 8) * 2 + half] = lh1;
        }
    }
    __syncthreads();
#pragma unroll
    for (int rep = 0; rep < 8; ++rep) {
        int idx = tid + rep * 512;
        int r = idx >> 5, cc = (idx & 31) * 2;
        float2 a = *(float2*)(Obuf + r * 64 + cc);
        float2 bb = *(float2*)(Obuf + (128 + r) * 64 + cc);
        float inv = 1.f / (mbuf[r * 2] + mbuf[r * 2 + 1]);
        uint32_t hv, lv;
        split2((a.x + bb.x) * inv, (a.y + bb.y) * inv, hv, lv);
        size_t off = (bh + (size_t)(qt * 128 + r)) * Kn + cc;
        *(uint32_t*)(g_oh + off) = hv;
        *(uint32_t*)(g_ol + off) = lv;
    }
}

// ===========================================================================
// mma.sync GEMM core: C[128 x 128] tile, BK=32, 8 warps (m32 x n64 each).
// Double-buffered smem (2 stages), ONE barrier per k-iteration.
// ===========================================================================
#define AS 40
#define BSS 136
#define STG_A (128 * AS)
#define STG_B (32 * BSS)
#define STG_E (2 * STG_A + 2 * STG_B)      // bf16 elems per stage
#define GEMM_SMEM (2 * STG_E * 2)          // bytes

struct MmaCtx {
    int wm, wn, l16, grp, lane;
};

__device__ __forceinline__ void mma_kblock(float (&acc)[2][8][4], uint32_t base,
                                           const MmaCtx& c) {
    const uint32_t sAh = base;
    const uint32_t sAl = base + STG_A * 2;
    const uint32_t sBh = base + STG_A * 4;
    const uint32_t sBl = base + STG_A * 4 + STG_B * 2;
#pragma unroll
    for (int ks = 0; ks < 32; ks += 16) {
        uint32_t ah[2][4], al[2][4];
#pragma unroll
        for (int mi = 0; mi < 2; ++mi) {
            const uint32_t aoff =
                (uint32_t)(((c.wm + mi * 16 + c.l16) * AS + ks + (c.lane >> 4) * 8) * 2);
            ldsm_x4(ah[mi], sAh + aoff);
            ldsm_x4(al[mi], sAl + aoff);
        }
        uint32_t bh[8][2], bl[8][2];
#pragma unroll
        for (int nb = 0; nb < 4; ++nb) {
            const uint32_t boff =
                (uint32_t)(((ks + (c.grp & 1) * 8 + (c.lane & 7)) * BSS +
                            c.wn + nb * 16 + (c.grp >> 1) * 8) * 2);
            uint32_t rh[4], rl[4];
            ldsm_x4t(rh, sBh + boff);
            ldsm_x4t(rl, sBl + boff);
            bh[2 * nb][0] = rh[0]; bh[2 * nb][1] = rh[1];
            bh[2 * nb + 1][0] = rh[2]; bh[2 * nb + 1][1] = rh[3];
            bl[2 * nb][0] = rl[0]; bl[2 * nb][1] = rl[1];
            bl[2 * nb + 1][0] = rl[2]; bl[2 * nb + 1][1] = rl[3];
        }
#pragma unroll
        for (int mi = 0; mi < 2; ++mi)
#pragma unroll
            for (int nj = 0; nj < 8; ++nj)
                mma_bf16(acc[mi][nj], ah[mi], bh[nj][0], bh[nj][1]);
#pragma unroll
        for (int mi = 0; mi < 2; ++mi)
#pragma unroll
            for (int nj = 0; nj < 8; ++nj)
                mma_bf16(acc[mi][nj], ah[mi], bl[nj][0], bl[nj][1]);
#pragma unroll
        for (int mi = 0; mi < 2; ++mi)
#pragma unroll
            for (int nj = 0; nj < 8; ++nj)
                mma_bf16(acc[mi][nj], al[mi], bh[nj][0], bh[nj][1]);
    }
}

// ---------------------------------------------------------------------------
// Merged QKV projection: blockIdx.z selects (X, W, out). Double-buffered.
// ---------------------------------------------------------------------------
struct ProjArgs {
    const float* X[3];
    const float* W[3];
    __nv_bfloat16* oh[3];
    __nv_bfloat16* ol[3];
};

__global__ __launch_bounds__(256) void proj_mma(ProjArgs args) {
    extern __shared__ __nv_bfloat16 gsm[];
    const uint32_t smb = smem_u32(gsm);
    const int z = blockIdx.z;
    const float* X = args.X[z];
    const float* W = args.W[z];
    __nv_bfloat16* oh = args.oh[z];
    __nv_bfloat16* ol = args.ol[z];

    const int tid = threadIdx.x;
    const int wid = tid >> 5, lane = tid & 31;
    MmaCtx c{(wid >> 1) * 32, (wid & 1) * 64, lane & 15, lane >> 3, lane};
    const int r0 = lane >> 2, c2 = (lane & 3) * 2;
    const int row0 = blockIdx.x * 128, c0 = blockIdx.y * 128;

    float acc[2][8][4] = {};
    float4 xr[4];
    float2 wr[8];

    auto load_regs = [&](int kk) {
#pragma unroll
        for (int rep = 0; rep < 4; ++rep) {
            int idx = tid + rep * 256;
            int r = idx >> 3, kc = (idx & 7) * 4;
            xr[rep] = *(const float4*)(X + (size_t)(row0 + r) * Dn + kk + kc);
        }
#pragma unroll
        for (int rep = 0; rep < 8; ++rep) {
            int idx = tid + rep * 256;
            int k = idx >> 6, col = (idx & 63) * 2;
            int colg = c0 + col;
            int h = colg >> 6, kidx = colg & 63;
            wr[rep] = *(const float2*)(W + (size_t)(h * Dn + kk + k) * Kn + kidx);
        }
    };

    load_regs(0);
    for (int it = 0; it < Dn / 32; ++it) {
        const int st = it & 1;
        __nv_bfloat16* Ah = gsm + st * STG_E;
        __nv_bfloat16* Al = Ah + STG_A;
        __nv_bfloat16* Bh = Al + STG_A;
        __nv_bfloat16* Bl = Bh + STG_B;
#pragma unroll
        for (int rep = 0; rep < 4; ++rep) {
            int idx = tid + rep * 256;
            int r = idx >> 3, kc = (idx & 7) * 4;
            uint32_t h0, l0, h1, l1;
            split2(xr[rep].x, xr[rep].y, h0, l0);
            split2(xr[rep].z, xr[rep].w, h1, l1);
            *(uint2*)&Ah[r * AS + kc] = make_uint2(h0, h1);
            *(uint2*)&Al[r * AS + kc] = make_uint2(l0, l1);
        }
#pragma unroll
        for (int rep = 0; rep < 8; ++rep) {
            int idx = tid + rep * 256;
            int k = idx >> 6, col = (idx & 63) * 2;
            uint32_t bh, bl;
            split2(wr[rep].x, wr[rep].y, bh, bl);
            *(uint32_t*)&Bh[k * BSS + col] = bh;
            *(uint32_t*)&Bl[k * BSS + col] = bl;
        }
        __syncthreads();
        if (it + 1 < Dn / 32) load_regs((it + 1) * 32);
        mma_kblock(acc, smb + (uint32_t)st * (STG_E * 2), c);
    }

#pragma unroll
    for (int mi = 0; mi < 2; ++mi)
#pragma unroll
        for (int rr = 0; rr < 2; ++rr) {
            int row = row0 + c.wm + mi * 16 + r0 + rr * 8;
            int b = row >> 11, s = row & 2047;
#pragma unroll
            for (int nj = 0; nj < 8; ++nj) {
                int colg = c0 + c.wn + nj * 8 + c2;
                int h = colg >> 6, k0 = colg & 63;
                size_t off = (((size_t)(b * Hn + h) * Sn + s) * Kn) + k0;
                uint32_t hv, lv;
                split2(acc[mi][nj][2 * rr], acc[mi][nj][2 * rr + 1], hv, lv);
                *(uint32_t*)(oh + off) = hv;
                *(uint32_t*)(ol + off) = lv;
            }
        }
}

// ---------------------------------------------------------------------------
// Output projection; A pre-split bf16; double-buffered.
// ---------------------------------------------------------------------------
__global__ __launch_bounds__(256) void outproj_mma(const __nv_bfloat16* __restrict__ Xh,
                                                   const __nv_bfloat16* __restrict__ Xl,
                                                   const float* __restrict__ Wo,
                                                   float* __restrict__ out) {
    extern __shared__ __nv_bfloat16 gsm[];
    const uint32_t smb = smem_u32(gsm);

    const int tid = threadIdx.x;
    const int wid = tid >> 5, lane = tid & 31;
    MmaCtx c{(wid >> 1) * 32, (wid & 1) * 64, lane & 15, lane >> 3, lane};
    const int r0 = lane >> 2, c2 = (lane & 3) * 2;
    const int row0 = blockIdx.x * 128, c0 = blockIdx.y * 128;

    float acc[2][8][4] = {};
    uint4 ar[2][2];
    float2 wr[8];

    auto load_regs = [&](int kk) {
#pragma unroll
        for (int rep = 0; rep < 2; ++rep) {
            int idx = tid + rep * 256;
            int r = idx >> 2, kc = (idx & 3) * 8;
            ar[rep][0] = *(const uint4*)(Xh + (size_t)(row0 + r) * Dn + kk + kc);
            ar[rep][1] = *(const uint4*)(Xl + (size_t)(row0 + r) * Dn + kk + kc);
        }
#pragma unroll
        for (int rep = 0; rep < 8; ++rep) {
            int idx = tid + rep * 256;
            int k = idx >> 6, col = (idx & 63) * 2;
            wr[rep] = *(const float2*)(Wo + (size_t)(kk + k) * Dn + c0 + col);
        }
    };

    load_regs(0);
    for (int it = 0; it < Dn / 32; ++it) {
        const int st = it & 1;
        __nv_bfloat16* Ah = gsm + st * STG_E;
        __nv_bfloat16* Al = Ah + STG_A;
        __nv_bfloat16* Bh = Al + STG_A;
        __nv_bfloat16* Bl = Bh + STG_B;
#pragma unroll
        for (int rep = 0; rep < 2; ++rep) {
            int idx = tid + rep * 256;
            int r = idx >> 2, kc = (idx & 3) * 8;
            *(uint4*)&Ah[r * AS + kc] = ar[rep][0];
            *(uint4*)&Al[r * AS + kc] = ar[rep][1];
        }
#pragma unroll
        for (int rep = 0; rep < 8; ++rep) {
            int idx = tid + rep * 256;
            int k = idx >> 6, col = (idx & 63) * 2;
            uint32_t bh, bl;
            split2(wr[rep].x, wr[rep].y, bh, bl);
            *(uint32_t*)&Bh[k * BSS + col] = bh;
            *(uint32_t*)&Bl[k * BSS + col] = bl;
        }
        __syncthreads();
        if (it + 1 < Dn / 32) load_regs((it + 1) * 32);
        mma_kblock(acc, smb + (uint32_t)st * (STG_E * 2), c);
    }

#pragma unroll
    for (int mi = 0; mi < 2; ++mi)
#pragma unroll
        for (int rr = 0; rr < 2; ++rr) {
            int row = row0 + c.wm + mi * 16 + r0 + rr * 8;
#pragma unroll
            for (int nj = 0; nj < 8; ++nj) {
                int colg = c0 + c.wn + nj * 8 + c2;
                *(float2*)(out + (size_t)row * Dn + colg) =
                    make_float2(acc[mi][nj][2 * rr], acc[mi][nj][2 * rr + 1]);
            }
        }
}

// ---------------------------------------------------------------------------
extern "C" void kernel_launch(void* const* d_in, const int* in_sizes, int n_in,
                              void* d_out, int out_size) {
    const float* queries = (const float*)d_in[0];
    const float* keys    = (const float*)d_in[1];
    const float* values  = (const float*)d_in[2];
    const float* mask    = (const float*)d_in[3];
    const float* W_q     = (const float*)d_in[4];
    const float* W_k     = (const float*)d_in[5];
    const float* W_v     = (const float*)d_in[6];
    const float* W_o     = (const float*)d_in[7];
    float* out = (float*)d_out;

    __nv_bfloat16 *qh, *ql, *kh, *kl, *vh, *vl, *oh, *ol;
    cudaGetSymbolAddress((void**)&qh, g_qh);
    cudaGetSymbolAddress((void**)&ql, g_ql);
    cudaGetSymbolAddress((void**)&kh, g_kh);
    cudaGetSymbolAddress((void**)&kl, g_kl);
    cudaGetSymbolAddress((void**)&vh, g_vh);
    cudaGetSymbolAddress((void**)&vl, g_vl);
    cudaGetSymbolAddress((void**)&oh, g_oh);
    cudaGetSymbolAddress((void**)&ol, g_ol);

    cudaFuncSetAttribute(attn_kernel, cudaFuncAttributeMaxDynamicSharedMemorySize, ATTN_SMEM);
    cudaFuncSetAttribute(proj_mma, cudaFuncAttributeMaxDynamicSharedMemorySize, GEMM_SMEM);
    cudaFuncSetAttribute(outproj_mma, cudaFuncAttributeMaxDynamicSharedMemorySize, GEMM_SMEM);

    ProjArgs pa;
    pa.X[0] = queries; pa.X[1] = keys; pa.X[2] = values;
    pa.W[0] = W_q;     pa.W[1] = W_k;  pa.W[2] = W_v;
    pa.oh[0] = qh;     pa.oh[1] = kh;  pa.oh[2] = vh;
    pa.ol[0] = ql;     pa.ol[1] = kl;  pa.ol[2] = vl;

    dim3 gproj(Bn * Sn / 128, Dn / 128, 3);  // (64, 6, 3)
    proj_mma<<<gproj, 256, GEMM_SMEM>>>(pa);

    dim3 gattn(Sn / 128, Hn, Bn);  // (16, 12, 4)
    attn_kernel<<<gattn, 512, ATTN_SMEM>>>(mask);

    dim3 gout(Bn * Sn / 128, Dn / 128);  // (64, 6)
    outproj_mma<<<gout, 256, GEMM_SMEM>>>(oh, ol, W_o, out);
}

// round 14
// speedup vs baseline: 1.2823x; 1.1191x over previous
#include <cuda_runtime.h>
#include <cuda_fp16.h>
#include <cstdint>

#define Bn 4
#define Sn 2048
#define Dn 768
#define Hn 12
#define Kn 64
#define NELEM (Bn * Hn * Sn * Kn)

// Scratch device globals (no cudaMalloc allowed). fp16 hi/lo pairs.
__device__ __half g_qh[NELEM];
__device__ __half g_kh[NELEM], g_kl[NELEM];
__device__ __half g_vh[NELEM], g_vl[NELEM];
__device__ __half g_oh[NELEM], g_ol[NELEM];
__device__ __half g_ql[NELEM];   // written by proj (shared epilogue), unused by attn

// ---------------------------------------------------------------------------
// helpers
// ---------------------------------------------------------------------------
__device__ __forceinline__ uint32_t smem_u32(const void* p) {
    uint32_t a;
    asm("{ .reg .u64 t; cvta.to.shared.u64 t, %1; cvt.u32.u64 %0, t; }" : "=r"(a) : "l"(p));
    return a;
}
__device__ __forceinline__ void ldsm_x4(uint32_t (&r)[4], uint32_t addr) {
    asm volatile("ldmatrix.sync.aligned.m8n8.x4.shared.b16 {%0,%1,%2,%3}, [%4];"
                 : "=r"(r[0]), "=r"(r[1]), "=r"(r[2]), "=r"(r[3]) : "r"(addr));
}
__device__ __forceinline__ void ldsm_x4t(uint32_t (&r)[4], uint32_t addr) {
    asm volatile("ldmatrix.sync.aligned.m8n8.x4.trans.shared.b16 {%0,%1,%2,%3}, [%4];"
                 : "=r"(r[0]), "=r"(r[1]), "=r"(r[2]), "=r"(r[3]) : "r"(addr));
}
__device__ __forceinline__ void mma_f16(float (&d)[4], const uint32_t (&a)[4],
                                        const uint32_t b0, const uint32_t b1) {
    asm volatile(
        "mma.sync.aligned.m16n8k16.row.col.f32.f16.f16.f32 "
        "{%0,%1,%2,%3}, {%4,%5,%6,%7}, {%8,%9}, {%0,%1,%2,%3};"
        : "+f"(d[0]), "+f"(d[1]), "+f"(d[2]), "+f"(d[3])
        : "r"(a[0]), "r"(a[1]), "r"(a[2]), "r"(a[3]), "r"(b0), "r"(b1));
}
// fp16 hi/lo split (11-bit mantissa per term -> ~22-bit pair)
__device__ __forceinline__ void split2(float x, float y, uint32_t& h, uint32_t& l) {
    __half hx = __float2half_rn(x), hy = __float2half_rn(y);
    __half lx = __float2half_rn(x - __half2float(hx));
    __half ly = __float2half_rn(y - __half2float(hy));
    __half2 hh = __halves2half2(hx, hy);
    __half2 ll = __halves2half2(lx, ly);
    h = *(uint32_t*)&hh;
    l = *(uint32_t*)&ll;
}
__device__ __forceinline__ uint32_t pack_h(float x, float y) {
    __half2 hh = __halves2half2(__float2half_rn(x), __float2half_rn(y));
    return *(uint32_t*)&hh;
}
__device__ __forceinline__ void cpa16(uint32_t dst, const void* src) {
    asm volatile("cp.async.cg.shared.global [%0], [%1], 16;" :: "r"(dst), "l"(src) : "memory");
}
__device__ __forceinline__ void cp_commit() { asm volatile("cp.async.commit_group;" ::: "memory"); }
__device__ __forceinline__ void cp_wait1() { asm volatile("cp.async.wait_group 1;" ::: "memory"); }

// ===========================================================================
// Attention: 512 threads / 16 warps. Warp (qw, half): qw = wid>>1 owns q rows
// [16qw,16qw+16), half = wid&1 owns S cols / kv rows [64half, 64half+64).
// cp.async double buffer, no-max softmax.
// fp16 2-term splits: S = qh*(kh+kl), O = Ph*(vh+vl).
// ===========================================================================
#define QS 72
#define TILE_E (128 * QS)
#define SM_MAXB (10 * TILE_E * 2)
#define ATTN_SMEM (SM_MAXB + 256 * 4)

__global__ __launch_bounds__(512, 1) void attn_kernel(const float* __restrict__ mask) {
    extern __shared__ __half smbf[];
    const uint32_t smb = smem_u32(smbf);
    const uint32_t sQh = smb;
    float* mbuf = (float*)((char*)smbf + SM_MAXB);
    float* Obuf = (float*)(smbf + 2 * TILE_E);

    const int tid = threadIdx.x;
    const int wid = tid >> 5, lane = tid & 31;
    const int qw = wid >> 1, half_i = wid & 1;
    const int cb = half_i * 64;
    const int l16 = lane & 15;
    const int g = lane >> 3;
    const int r0 = lane >> 2;
    const int c2 = (lane & 3) * 2;
    const int qt = blockIdx.x, hd = blockIdx.y, b = blockIdx.z;
    const size_t bh = (size_t)(b * Hn + hd) * Sn;
    const int qr0 = qw * 16;
    const int qg0 = qt * 128 + qr0;

    const int ld_r = tid >> 3, ld_c = (tid & 7) * 8;
    const int ld_r1 = (tid + 512) >> 3;

    // Q tile hi only.
    {
        const __half* qh = g_qh + (bh + (size_t)qt * 128) * Kn;
#pragma unroll
        for (int rep = 0; rep < 2; ++rep) {
            int r = rep ? ld_r1 : ld_r;
            *(uint4*)(smbf + r * QS + ld_c) = *(const uint4*)(qh + r * 64 + ld_c);
        }
    }

    auto issue_tile = [&](int kt2, int st) {
        const __half* kh = g_kh + (bh + (size_t)kt2 * 128) * Kn;
        const __half* kl = g_kl + (bh + (size_t)kt2 * 128) * Kn;
        const __half* vh = g_vh + (bh + (size_t)kt2 * 128) * Kn;
        const __half* vl = g_vl + (bh + (size_t)kt2 * 128) * Kn;
        const uint32_t base = smb + (uint32_t)(2 + st * 4) * (TILE_E * 2);
#pragma unroll
        for (int rep = 0; rep < 2; ++rep) {
            int r = rep ? ld_r1 : ld_r;
            uint32_t off = (uint32_t)(r * QS + ld_c) * 2;
            cpa16(base + off, kh + r * 64 + ld_c);
            cpa16(base + TILE_E * 2 + off, kl + r * 64 + ld_c);
            cpa16(base + TILE_E * 4 + off, vh + r * 64 + ld_c);
            cpa16(base + TILE_E * 6 + off, vl + r * 64 + ld_c);
        }
    };

    issue_tile(0, 0);
    cp_commit();
    issue_tile(1, 1);
    cp_commit();

    float oacc[8][4];
#pragma unroll
    for (int n = 0; n < 8; ++n)
#pragma unroll
        for (int j = 0; j < 4; ++j) oacc[n][j] = 0.f;
    float lh0 = 0.f, lh1 = 0.f;

    const float* mp0 = mask + (size_t)(qg0 + r0) * Sn;
    const float* mp1 = mp0 + 8 * Sn;
    const float scale = 0.125f;

    for (int kt = 0; kt < Sn / 128; ++kt) {
        const int st = kt & 1;
        const uint32_t sKh = smb + (uint32_t)(2 + st * 4) * (TILE_E * 2);
        const uint32_t sKl = sKh + TILE_E * 2;
        const uint32_t sVh = sKh + TILE_E * 4;
        const uint32_t sVl = sKh + TILE_E * 6;

        cp_wait1();
        __syncthreads();

        // ---- S = Qh @ (Kh + Kl)^T: 2 fp16 terms ----
        float sacc[8][4];
#pragma unroll
        for (int n = 0; n < 8; ++n)
#pragma unroll
            for (int j = 0; j < 4; ++j) sacc[n][j] = 0.f;

#pragma unroll
        for (int ks = 0; ks < 4; ++ks) {
            uint32_t aqh[4];
            const uint32_t aoff =
                (uint32_t)(((qr0 + l16) * QS + ks * 16 + (lane >> 4) * 8) * 2);
            ldsm_x4(aqh, sQh + aoff);
            uint32_t rh[4][4], rl[4][4];
#pragma unroll
            for (int n2 = 0; n2 < 4; ++n2) {
                const uint32_t boff =
                    (uint32_t)(((cb + n2 * 16 + (g >> 1) * 8 + (lane & 7)) * QS +
                                ks * 16 + (g & 1) * 8) * 2);
                ldsm_x4(rh[n2], sKh + boff);
                ldsm_x4(rl[n2], sKl + boff);
            }
#pragma unroll
            for (int n2 = 0; n2 < 4; ++n2) {
                mma_f16(sacc[2 * n2], aqh, rh[n2][0], rh[n2][1]);
                mma_f16(sacc[2 * n2 + 1], aqh, rh[n2][2], rh[n2][3]);
            }
#pragma unroll
            for (int n2 = 0; n2 < 4; ++n2) {
                mma_f16(sacc[2 * n2], aqh, rl[n2][0], rl[n2][1]);
                mma_f16(sacc[2 * n2 + 1], aqh, rl[n2][2], rl[n2][3]);
            }
        }

        // ---- scale + mask bias + exp (no max subtraction) ----
#pragma unroll
        for (int n = 0; n < 8; ++n) {
            const int col = kt * 128 + cb + n * 8 + c2;
            float2 mv0 = __ldg((const float2*)(mp0 + col));
            float2 mv1 = __ldg((const float2*)(mp1 + col));
            sacc[n][0] = __expf(fmaf(sacc[n][0], scale, (1.f - mv0.x) * -1e9f));
            sacc[n][1] = __expf(fmaf(sacc[n][1], scale, (1.f - mv0.y) * -1e9f));
            sacc[n][2] = __expf(fmaf(sacc[n][2], scale, (1.f - mv1.x) * -1e9f));
            sacc[n][3] = __expf(fmaf(sacc[n][3], scale, (1.f - mv1.y) * -1e9f));
            lh0 += sacc[n][0] + sacc[n][1];
            lh1 += sacc[n][2] + sacc[n][3];
        }

        // ---- O_half += Ph @ (Vh + Vl): 2 fp16 terms ----
#pragma unroll
        for (int j = 0; j < 4; ++j) {
            uint32_t ah[4];
            ah[0] = pack_h(sacc[2 * j][0], sacc[2 * j][1]);
            ah[1] = pack_h(sacc[2 * j][2], sacc[2 * j][3]);
            ah[2] = pack_h(sacc[2 * j + 1][0], sacc[2 * j + 1][1]);
            ah[3] = pack_h(sacc[2 * j + 1][2], sacc[2 * j + 1][3]);
            uint32_t rh[4][4], rl[4][4];
#pragma unroll
            for (int nv2 = 0; nv2 < 4; ++nv2) {
                const uint32_t voff =
                    (uint32_t)(((cb + j * 16 + (g & 1) * 8 + (lane & 7)) * QS +
                                nv2 * 16 + (g >> 1) * 8) * 2);
                ldsm_x4t(rh[nv2], sVh + voff);
                ldsm_x4t(rl[nv2], sVl + voff);
            }
#pragma unroll
            for (int nv2 = 0; nv2 < 4; ++nv2) {
                mma_f16(oacc[2 * nv2], ah, rh[nv2][0], rh[nv2][1]);
                mma_f16(oacc[2 * nv2 + 1], ah, rh[nv2][2], rh[nv2][3]);
            }
#pragma unroll
            for (int nv2 = 0; nv2 < 4; ++nv2) {
                mma_f16(oacc[2 * nv2], ah, rl[nv2][0], rl[nv2][1]);
                mma_f16(oacc[2 * nv2 + 1], ah, rl[nv2][2], rl[nv2][3]);
            }
        }

        __syncthreads();
        if (kt + 2 < Sn / 128) issue_tile(kt + 2, st);
        cp_commit();
    }

#pragma unroll
    for (int w = 1; w < 4; w <<= 1) {
        lh0 += __shfl_xor_sync(0xffffffffu, lh0, w);
        lh1 += __shfl_xor_sync(0xffffffffu, lh1, w);
    }
    {
        float* Ow = Obuf + (size_t)half_i * 128 * 64;
#pragma unroll
        for (int nv = 0; nv < 8; ++nv) {
            *(float2*)(Ow + (qr0 + r0) * 64 + nv * 8 + c2) =
                make_float2(oacc[nv][0], oacc[nv][1]);
            *(float2*)(Ow + (qr0 + r0 + 8) * 64 + nv * 8 + c2) =
                make_float2(oacc[nv][2], oacc[nv][3]);
        }
        if ((lane & 3) == 0) {
            mbuf[(qr0 + r0) * 2 + half_i] = lh0;
            mbuf[(qr0 + r0 + 8) * 2 + half_i] = lh1;
        }
    }
    __syncthreads();
#pragma unroll
    for (int rep = 0; rep < 8; ++rep) {
        int idx = tid + rep * 512;
        int r = idx >> 5, cc = (idx & 31) * 2;
        float2 a = *(float2*)(Obuf + r * 64 + cc);
        float2 bb = *(float2*)(Obuf + (128 + r) * 64 + cc);
        float inv = 1.f / (mbuf[r * 2] + mbuf[r * 2 + 1]);
        uint32_t hv, lv;
        split2((a.x + bb.x) * inv, (a.y + bb.y) * inv, hv, lv);
        size_t off = (bh + (size_t)(qt * 128 + r)) * Kn + cc;
        *(uint32_t*)(g_oh + off) = hv;
        *(uint32_t*)(g_ol + off) = lv;
    }
}

// ===========================================================================
// mma.sync GEMM core: C[128 x 128] tile, BK=32, 8 warps (m32 x n64 each).
// fp16 3-term split, double-buffered smem, ONE barrier per k-iteration.
// ===========================================================================
#define AS 40
#define BSS 136
#define STG_A (128 * AS)
#define STG_B (32 * BSS)
#define STG_E (2 * STG_A + 2 * STG_B)
#define GEMM_SMEM (2 * STG_E * 2)

struct MmaCtx {
    int wm, wn, l16, grp, lane;
};

__device__ __forceinline__ void mma_kblock(float (&acc)[2][8][4], uint32_t base,
                                           const MmaCtx& c) {
    const uint32_t sAh = base;
    const uint32_t sAl = base + STG_A * 2;
    const uint32_t sBh = base + STG_A * 4;
    const uint32_t sBl = base + STG_A * 4 + STG_B * 2;
#pragma unroll
    for (int ks = 0; ks < 32; ks += 16) {
        uint32_t ah[2][4], al[2][4];
#pragma unroll
        for (int mi = 0; mi < 2; ++mi) {
            const uint32_t aoff =
                (uint32_t)(((c.wm + mi * 16 + c.l16) * AS + ks + (c.lane >> 4) * 8) * 2);
            ldsm_x4(ah[mi], sAh + aoff);
            ldsm_x4(al[mi], sAl + aoff);
        }
        uint32_t bh[8][2], bl[8][2];
#pragma unroll
        for (int nb = 0; nb < 4; ++nb) {
            const uint32_t boff =
                (uint32_t)(((ks + (c.grp & 1) * 8 + (c.lane & 7)) * BSS +
                            c.wn + nb * 16 + (c.grp >> 1) * 8) * 2);
            uint32_t rh[4], rl[4];
            ldsm_x4t(rh, sBh + boff);
            ldsm_x4t(rl, sBl + boff);
            bh[2 * nb][0] = rh[0]; bh[2 * nb][1] = rh[1];
            bh[2 * nb + 1][0] = rh[2]; bh[2 * nb + 1][1] = rh[3];
            bl[2 * nb][0] = rl[0]; bl[2 * nb][1] = rl[1];
            bl[2 * nb + 1][0] = rl[2]; bl[2 * nb + 1][1] = rl[3];
        }
#pragma unroll
        for (int mi = 0; mi < 2; ++mi)
#pragma unroll
            for (int nj = 0; nj < 8; ++nj)
                mma_f16(acc[mi][nj], ah[mi], bh[nj][0], bh[nj][1]);
#pragma unroll
        for (int mi = 0; mi < 2; ++mi)
#pragma unroll
            for (int nj = 0; nj < 8; ++nj)
                mma_f16(acc[mi][nj], ah[mi], bl[nj][0], bl[nj][1]);
#pragma unroll
        for (int mi = 0; mi < 2; ++mi)
#pragma unroll
            for (int nj = 0; nj < 8; ++nj)
                mma_f16(acc[mi][nj], al[mi], bh[nj][0], bh[nj][1]);
    }
}

// ---------------------------------------------------------------------------
// Merged QKV projection: blockIdx.z selects (X, W, out). Double-buffered.
// ---------------------------------------------------------------------------
struct ProjArgs {
    const float* X[3];
    const float* W[3];
    __half* oh[3];
    __half* ol[3];
};

__global__ __launch_bounds__(256) void proj_mma(ProjArgs args) {
    extern __shared__ __half gsm[];
    const uint32_t smb = smem_u32(gsm);
    const int z = blockIdx.z;
    const float* X = args.X[z];
    const float* W = args.W[z];
    __half* oh = args.oh[z];
    __half* ol = args.ol[z];

    const int tid = threadIdx.x;
    const int wid = tid >> 5, lane = tid & 31;
    MmaCtx c{(wid >> 1) * 32, (wid & 1) * 64, lane & 15, lane >> 3, lane};
    const int r0 = lane >> 2, c2 = (lane & 3) * 2;
    const int row0 = blockIdx.x * 128, c0 = blockIdx.y * 128;

    float acc[2][8][4] = {};
    float4 xr[4];
    float2 wr[8];

    auto load_regs = [&](int kk) {
#pragma unroll
        for (int rep = 0; rep < 4; ++rep) {
            int idx = tid + rep * 256;
            int r = idx >> 3, kc = (idx & 7) * 4;
            xr[rep] = *(const float4*)(X + (size_t)(row0 + r) * Dn + kk + kc);
        }
#pragma unroll
        for (int rep = 0; rep < 8; ++rep) {
            int idx = tid + rep * 256;
            int k = idx >> 6, col = (idx & 63) * 2;
            int colg = c0 + col;
            int h = colg >> 6, kidx = colg & 63;
            wr[rep] = *(const float2*)(W + (size_t)(h * Dn + kk + k) * Kn + kidx);
        }
    };

    load_regs(0);
    for (int it = 0; it < Dn / 32; ++it) {
        const int st = it & 1;
        __half* Ah = gsm + st * STG_E;
        __half* Al = Ah + STG_A;
        __half* Bh = Al + STG_A;
        __half* Bl = Bh + STG_B;
#pragma unroll
        for (int rep = 0; rep < 4; ++rep) {
            int idx = tid + rep * 256;
            int r = idx >> 3, kc = (idx & 7) * 4;
            uint32_t h0, l0, h1, l1;
            split2(xr[rep].x, xr[rep].y, h0, l0);
            split2(xr[rep].z, xr[rep].w, h1, l1);
            *(uint2*)&Ah[r * AS + kc] = make_uint2(h0, h1);
            *(uint2*)&Al[r * AS + kc] = make_uint2(l0, l1);
        }
#pragma unroll
        for (int rep = 0; rep < 8; ++rep) {
            int idx = tid + rep * 256;
            int k = idx >> 6, col = (idx & 63) * 2;
            uint32_t bh, bl;
            split2(wr[rep].x, wr[rep].y, bh, bl);
            *(uint32_t*)&Bh[k * BSS + col] = bh;
            *(uint32_t*)&Bl[k * BSS + col] = bl;
        }
        __syncthreads();
        if (it + 1 < Dn / 32) load_regs((it + 1) * 32);
        mma_kblock(acc, smb + (uint32_t)st * (STG_E * 2), c);
    }

#pragma unroll
    for (int mi = 0; mi < 2; ++mi)
#pragma unroll
        for (int rr = 0; rr < 2; ++rr) {
            int row = row0 + c.wm + mi * 16 + r0 + rr * 8;
            int b = row >> 11, s = row & 2047;
#pragma unroll
            for (int nj = 0; nj < 8; ++nj) {
                int colg = c0 + c.wn + nj * 8 + c2;
                int h = colg >> 6, k0 = colg & 63;
                size_t off = (((size_t)(b * Hn + h) * Sn + s) * Kn) + k0;
                uint32_t hv, lv;
                split2(acc[mi][nj][2 * rr], acc[mi][nj][2 * rr + 1], hv, lv);
                *(uint32_t*)(oh + off) = hv;
                *(uint32_t*)(ol + off) = lv;
            }
        }
}

// ---------------------------------------------------------------------------
// Output projection; A pre-split fp16; double-buffered.
// ---------------------------------------------------------------------------
__global__ __launch_bounds__(256) void outproj_mma(const __half* __restrict__ Xh,
                                                   const __half* __restrict__ Xl,
                                                   const float* __restrict__ Wo,
                                                   float* __restrict__ out) {
    extern __shared__ __half gsm[];
    const uint32_t smb = smem_u32(gsm);

    const int tid = threadIdx.x;
    const int wid = tid >> 5, lane = tid & 31;
    MmaCtx c{(wid >> 1) * 32, (wid & 1) * 64, lane & 15, lane >> 3, lane};
    const int r0 = lane >> 2, c2 = (lane & 3) * 2;
    const int row0 = blockIdx.x * 128, c0 = blockIdx.y * 128;

    float acc[2][8][4] = {};
    uint4 ar[2][2];
    float2 wr[8];

    auto load_regs = [&](int kk) {
#pragma unroll
        for (int rep = 0; rep < 2; ++rep) {
            int idx = tid + rep * 256;
            int r = idx >> 2, kc = (idx & 3) * 8;
            ar[rep][0] = *(const uint4*)(Xh + (size_t)(row0 + r) * Dn + kk + kc);
            ar[rep][1] = *(const uint4*)(Xl + (size_t)(row0 + r) * Dn + kk + kc);
        }
#pragma unroll
        for (int rep = 0; rep < 8; ++rep) {
            int idx = tid + rep * 256;
            int k = idx >> 6, col = (idx & 63) * 2;
            wr[rep] = *(const float2*)(Wo + (size_t)(kk + k) * Dn + c0 + col);
        }
    };

    load_regs(0);
    for (int it = 0; it < Dn / 32; ++it) {
        const int st = it & 1;
        __half* Ah = gsm + st * STG_E;
        __half* Al = Ah + STG_A;
        __half* Bh = Al + STG_A;
        __half* Bl = Bh + STG_B;
#pragma unroll
        for (int rep = 0; rep < 2; ++rep) {
            int idx = tid + rep * 256;
            int r = idx >> 2, kc = (idx & 3) * 8;
            *(uint4*)&Ah[r * AS + kc] = ar[rep][0];
            *(uint4*)&Al[r * AS + kc] = ar[rep][1];
        }
#pragma unroll
        for (int rep = 0; rep < 8; ++rep) {
            int idx = tid + rep * 256;
            int k = idx >> 6, col = (idx & 63) * 2;
            uint32_t bh, bl;
            split2(wr[rep].x, wr[rep].y, bh, bl);
            *(uint32_t*)&Bh[k * BSS + col] = bh;
            *(uint32_t*)&Bl[k * BSS + col] = bl;
        }
        __syncthreads();
        if (it + 1 < Dn / 32) load_regs((it + 1) * 32);
        mma_kblock(acc, smb + (uint32_t)st * (STG_E * 2), c);
    }

#pragma unroll
    for (int mi = 0; mi < 2; ++mi)
#pragma unroll
        for (int rr = 0; rr < 2; ++rr) {
            int row = row0 + c.wm + mi * 16 + r0 + rr * 8;
#pragma unroll
            for (int nj = 0; nj < 8; ++nj) {
                int colg = c0 + c.wn + nj * 8 + c2;
                *(float2*)(out + (size_t)row * Dn + colg) =
                    make_float2(acc[mi][nj][2 * rr], acc[mi][nj][2 * rr + 1]);
            }
        }
}

// ---------------------------------------------------------------------------
extern "C" void kernel_launch(void* const* d_in, const int* in_sizes, int n_in,
                              void* d_out, int out_size) {
    const float* queries = (const float*)d_in[0];
    const float* keys    = (const float*)d_in[1];
    const float* values  = (const float*)d_in[2];
    const float* mask    = (const float*)d_in[3];
    const float* W_q     = (const float*)d_in[4];
    const float* W_k     = (const float*)d_in[5];
    const float* W_v     = (const float*)d_in[6];
    const float* W_o     = (const float*)d_in[7];
    float* out = (float*)d_out;

    __half *qh, *ql, *kh, *kl, *vh, *vl, *oh, *ol;
    cudaGetSymbolAddress((void**)&qh, g_qh);
    cudaGetSymbolAddress((void**)&ql, g_ql);
    cudaGetSymbolAddress((void**)&kh, g_kh);
    cudaGetSymbolAddress((void**)&kl, g_kl);
    cudaGetSymbolAddress((void**)&vh, g_vh);
    cudaGetSymbolAddress((void**)&vl, g_vl);
    cudaGetSymbolAddress((void**)&oh, g_oh);
    cudaGetSymbolAddress((void**)&ol, g_ol);

    cudaFuncSetAttribute(attn_kernel, cudaFuncAttributeMaxDynamicSharedMemorySize, ATTN_SMEM);
    cudaFuncSetAttribute(proj_mma, cudaFuncAttributeMaxDynamicSharedMemorySize, GEMM_SMEM);
    cudaFuncSetAttribute(outproj_mma, cudaFuncAttributeMaxDynamicSharedMemorySize, GEMM_SMEM);

    ProjArgs pa;
    pa.X[0] = queries; pa.X[1] = keys; pa.X[2] = values;
    pa.W[0] = W_q;     pa.W[1] = W_k;  pa.W[2] = W_v;
    pa.oh[0] = qh;     pa.oh[1] = kh;  pa.oh[2] = vh;
    pa.ol[0] = ql;     pa.ol[1] = kl;  pa.ol[2] = vl;

    dim3 gproj(Bn * Sn / 128, Dn / 128, 3);  // (64, 6, 3)
    proj_mma<<<gproj, 256, GEMM_SMEM>>>(pa);

    dim3 gattn(Sn / 128, Hn, Bn);  // (16, 12, 4)
    attn_kernel<<<gattn, 512, ATTN_SMEM>>>(mask);

    dim3 gout(Bn * Sn / 128, Dn / 128);  // (64, 6)
    outproj_mma<<<gout, 256, GEMM_SMEM>>>(oh, ol, W_o, out);
}

// round 15
// speedup vs baseline: 1.4462x; 1.1279x over previous
#include <cuda_runtime.h>
#include <cuda_fp16.h>
#include <cstdint>

#define Bn 4
#define Sn 2048
#define Dn 768
#define Hn 12
#define Kn 64
#define NELEM (Bn * Hn * Sn * Kn)

// Scratch device globals (no cudaMalloc allowed). fp16.
__device__ __half g_qh[NELEM];
__device__ __half g_kh[NELEM], g_kl[NELEM];
__device__ __half g_vh[NELEM], g_vl[NELEM];
__device__ __half g_oh[NELEM];
__device__ __half g_ql[NELEM];   // q-lo written by shared proj epilogue, unused

// ---------------------------------------------------------------------------
// helpers
// ---------------------------------------------------------------------------
__device__ __forceinline__ uint32_t smem_u32(const void* p) {
    uint32_t a;
    asm("{ .reg .u64 t; cvta.to.shared.u64 t, %1; cvt.u32.u64 %0, t; }" : "=r"(a) : "l"(p));
    return a;
}
__device__ __forceinline__ void ldsm_x4(uint32_t (&r)[4], uint32_t addr) {
    asm volatile("ldmatrix.sync.aligned.m8n8.x4.shared.b16 {%0,%1,%2,%3}, [%4];"
                 : "=r"(r[0]), "=r"(r[1]), "=r"(r[2]), "=r"(r[3]) : "r"(addr));
}
__device__ __forceinline__ void ldsm_x4t(uint32_t (&r)[4], uint32_t addr) {
    asm volatile("ldmatrix.sync.aligned.m8n8.x4.trans.shared.b16 {%0,%1,%2,%3}, [%4];"
                 : "=r"(r[0]), "=r"(r[1]), "=r"(r[2]), "=r"(r[3]) : "r"(addr));
}
__device__ __forceinline__ void mma_f16(float (&d)[4], const uint32_t (&a)[4],
                                        const uint32_t b0, const uint32_t b1) {
    asm volatile(
        "mma.sync.aligned.m16n8k16.row.col.f32.f16.f16.f32 "
        "{%0,%1,%2,%3}, {%4,%5,%6,%7}, {%8,%9}, {%0,%1,%2,%3};"
        : "+f"(d[0]), "+f"(d[1]), "+f"(d[2]), "+f"(d[3])
        : "r"(a[0]), "r"(a[1]), "r"(a[2]), "r"(a[3]), "r"(b0), "r"(b1));
}
__device__ __forceinline__ void split2(float x, float y, uint32_t& h, uint32_t& l) {
    __half hx = __float2half_rn(x), hy = __float2half_rn(y);
    __half lx = __float2half_rn(x - __half2float(hx));
    __half ly = __float2half_rn(y - __half2float(hy));
    __half2 hh = __halves2half2(hx, hy);
    __half2 ll = __halves2half2(lx, ly);
    h = *(uint32_t*)&hh;
    l = *(uint32_t*)&ll;
}
__device__ __forceinline__ uint32_t pack_h(float x, float y) {
    __half2 hh = __halves2half2(__float2half_rn(x), __float2half_rn(y));
    return *(uint32_t*)&hh;
}
__device__ __forceinline__ void cpa16(uint32_t dst, const void* src) {
    asm volatile("cp.async.cg.shared.global [%0], [%1], 16;" :: "r"(dst), "l"(src) : "memory");
}
__device__ __forceinline__ void cp_commit() { asm volatile("cp.async.commit_group;" ::: "memory"); }
__device__ __forceinline__ void cp_wait1() { asm volatile("cp.async.wait_group 1;" ::: "memory"); }

// ===========================================================================
// Attention: 512 threads / 16 warps (R14 winner). Warp (qw, half):
// qw = wid>>1 owns q rows [16qw,16qw+16), half = wid&1 owns S cols / kv rows
// [64half, 64half+64). cp.async double buffer, no-max softmax.
// fp16 2-term: S = qh*(kh+kl), O = Ph*(vh+vl). Output: fp16 hi only.
// ===========================================================================
#define QS 72
#define TILE_E (128 * QS)
#define SM_MAXB (10 * TILE_E * 2)
#define ATTN_SMEM (SM_MAXB + 256 * 4)

__global__ __launch_bounds__(512, 1) void attn_kernel(const float* __restrict__ mask) {
    extern __shared__ __half smbf[];
    const uint32_t smb = smem_u32(smbf);
    const uint32_t sQh = smb;
    float* mbuf = (float*)((char*)smbf + SM_MAXB);
    float* Obuf = (float*)(smbf + 2 * TILE_E);

    const int tid = threadIdx.x;
    const int wid = tid >> 5, lane = tid & 31;
    const int qw = wid >> 1, half_i = wid & 1;
    const int cb = half_i * 64;
    const int l16 = lane & 15;
    const int g = lane >> 3;
    const int r0 = lane >> 2;
    const int c2 = (lane & 3) * 2;
    const int qt = blockIdx.x, hd = blockIdx.y, b = blockIdx.z;
    const size_t bh = (size_t)(b * Hn + hd) * Sn;
    const int qr0 = qw * 16;
    const int qg0 = qt * 128 + qr0;

    const int ld_r = tid >> 3, ld_c = (tid & 7) * 8;
    const int ld_r1 = (tid + 512) >> 3;

    {
        const __half* qh = g_qh + (bh + (size_t)qt * 128) * Kn;
#pragma unroll
        for (int rep = 0; rep < 2; ++rep) {
            int r = rep ? ld_r1 : ld_r;
            *(uint4*)(smbf + r * QS + ld_c) = *(const uint4*)(qh + r * 64 + ld_c);
        }
    }

    auto issue_tile = [&](int kt2, int st) {
        const __half* kh = g_kh + (bh + (size_t)kt2 * 128) * Kn;
        const __half* kl = g_kl + (bh + (size_t)kt2 * 128) * Kn;
        const __half* vh = g_vh + (bh + (size_t)kt2 * 128) * Kn;
        const __half* vl = g_vl + (bh + (size_t)kt2 * 128) * Kn;
        const uint32_t base = smb + (uint32_t)(2 + st * 4) * (TILE_E * 2);
#pragma unroll
        for (int rep = 0; rep < 2; ++rep) {
            int r = rep ? ld_r1 : ld_r;
            uint32_t off = (uint32_t)(r * QS + ld_c) * 2;
            cpa16(base + off, kh + r * 64 + ld_c);
            cpa16(base + TILE_E * 2 + off, kl + r * 64 + ld_c);
            cpa16(base + TILE_E * 4 + off, vh + r * 64 + ld_c);
            cpa16(base + TILE_E * 6 + off, vl + r * 64 + ld_c);
        }
    };

    issue_tile(0, 0);
    cp_commit();
    issue_tile(1, 1);
    cp_commit();

    float oacc[8][4];
#pragma unroll
    for (int n = 0; n < 8; ++n)
#pragma unroll
        for (int j = 0; j < 4; ++j) oacc[n][j] = 0.f;
    float lh0 = 0.f, lh1 = 0.f;

    const float* mp0 = mask + (size_t)(qg0 + r0) * Sn;
    const float* mp1 = mp0 + 8 * Sn;
    const float scale = 0.125f;

    for (int kt = 0; kt < Sn / 128; ++kt) {
        const int st = kt & 1;
        const uint32_t sKh = smb + (uint32_t)(2 + st * 4) * (TILE_E * 2);
        const uint32_t sKl = sKh + TILE_E * 2;
        const uint32_t sVh = sKh + TILE_E * 4;
        const uint32_t sVl = sKh + TILE_E * 6;

        cp_wait1();
        __syncthreads();

        float sacc[8][4];
#pragma unroll
        for (int n = 0; n < 8; ++n)
#pragma unroll
            for (int j = 0; j < 4; ++j) sacc[n][j] = 0.f;

#pragma unroll
        for (int ks = 0; ks < 4; ++ks) {
            uint32_t aqh[4];
            const uint32_t aoff =
                (uint32_t)(((qr0 + l16) * QS + ks * 16 + (lane >> 4) * 8) * 2);
            ldsm_x4(aqh, sQh + aoff);
            uint32_t rh[4][4], rl[4][4];
#pragma unroll
            for (int n2 = 0; n2 < 4; ++n2) {
                const uint32_t boff =
                    (uint32_t)(((cb + n2 * 16 + (g >> 1) * 8 + (lane & 7)) * QS +
                                ks * 16 + (g & 1) * 8) * 2);
                ldsm_x4(rh[n2], sKh + boff);
                ldsm_x4(rl[n2], sKl + boff);
            }
#pragma unroll
            for (int n2 = 0; n2 < 4; ++n2) {
                mma_f16(sacc[2 * n2], aqh, rh[n2][0], rh[n2][1]);
                mma_f16(sacc[2 * n2 + 1], aqh, rh[n2][2], rh[n2][3]);
            }
#pragma unroll
            for (int n2 = 0; n2 < 4; ++n2) {
                mma_f16(sacc[2 * n2], aqh, rl[n2][0], rl[n2][1]);
                mma_f16(sacc[2 * n2 + 1], aqh, rl[n2][2], rl[n2][3]);
            }
        }

#pragma unroll
        for (int n = 0; n < 8; ++n) {
            const int col = kt * 128 + cb + n * 8 + c2;
            float2 mv0 = __ldg((const float2*)(mp0 + col));
            float2 mv1 = __ldg((const float2*)(mp1 + col));
            sacc[n][0] = __expf(fmaf(sacc[n][0], scale, (1.f - mv0.x) * -1e9f));
            sacc[n][1] = __expf(fmaf(sacc[n][1], scale, (1.f - mv0.y) * -1e9f));
            sacc[n][2] = __expf(fmaf(sacc[n][2], scale, (1.f - mv1.x) * -1e9f));
            sacc[n][3] = __expf(fmaf(sacc[n][3], scale, (1.f - mv1.y) * -1e9f));
            lh0 += sacc[n][0] + sacc[n][1];
            lh1 += sacc[n][2] + sacc[n][3];
        }

#pragma unroll
        for (int j = 0; j < 4; ++j) {
            uint32_t ah[4];
            ah[0] = pack_h(sacc[2 * j][0], sacc[2 * j][1]);
            ah[1] = pack_h(sacc[2 * j][2], sacc[2 * j][3]);
            ah[2] = pack_h(sacc[2 * j + 1][0], sacc[2 * j + 1][1]);
            ah[3] = pack_h(sacc[2 * j + 1][2], sacc[2 * j + 1][3]);
            uint32_t rh[4][4], rl[4][4];
#pragma unroll
            for (int nv2 = 0; nv2 < 4; ++nv2) {
                const uint32_t voff =
                    (uint32_t)(((cb + j * 16 + (g & 1) * 8 + (lane & 7)) * QS +
                                nv2 * 16 + (g >> 1) * 8) * 2);
                ldsm_x4t(rh[nv2], sVh + voff);
                ldsm_x4t(rl[nv2], sVl + voff);
            }
#pragma unroll
            for (int nv2 = 0; nv2 < 4; ++nv2) {
                mma_f16(oacc[2 * nv2], ah, rh[nv2][0], rh[nv2][1]);
                mma_f16(oacc[2 * nv2 + 1], ah, rh[nv2][2], rh[nv2][3]);
            }
#pragma unroll
            for (int nv2 = 0; nv2 < 4; ++nv2) {
                mma_f16(oacc[2 * nv2], ah, rl[nv2][0], rl[nv2][1]);
                mma_f16(oacc[2 * nv2 + 1], ah, rl[nv2][2], rl[nv2][3]);
            }
        }

        __syncthreads();
        if (kt + 2 < Sn / 128) issue_tile(kt + 2, st);
        cp_commit();
    }

#pragma unroll
    for (int w = 1; w < 4; w <<= 1) {
        lh0 += __shfl_xor_sync(0xffffffffu, lh0, w);
        lh1 += __shfl_xor_sync(0xffffffffu, lh1, w);
    }
    {
        float* Ow = Obuf + (size_t)half_i * 128 * 64;
#pragma unroll
        for (int nv = 0; nv < 8; ++nv) {
            *(float2*)(Ow + (qr0 + r0) * 64 + nv * 8 + c2) =
                make_float2(oacc[nv][0], oacc[nv][1]);
            *(float2*)(Ow + (qr0 + r0 + 8) * 64 + nv * 8 + c2) =
                make_float2(oacc[nv][2], oacc[nv][3]);
        }
        if ((lane & 3) == 0) {
            mbuf[(qr0 + r0) * 2 + half_i] = lh0;
            mbuf[(qr0 + r0 + 8) * 2 + half_i] = lh1;
        }
    }
    __syncthreads();
    // merge halves, normalize, store fp16 hi only
#pragma unroll
    for (int rep = 0; rep < 8; ++rep) {
        int idx = tid + rep * 512;
        int r = idx >> 5, cc = (idx & 31) * 2;
        float2 a = *(float2*)(Obuf + r * 64 + cc);
        float2 bb = *(float2*)(Obuf + (128 + r) * 64 + cc);
        float inv = 1.f / (mbuf[r * 2] + mbuf[r * 2 + 1]);
        size_t off = (bh + (size_t)(qt * 128 + r)) * Kn + cc;
        *(uint32_t*)(g_oh + off) = pack_h((a.x + bb.x) * inv, (a.y + bb.y) * inv);
    }
}

// ===========================================================================
// mma.sync GEMM core (2-term): C[128 x 128] tile, BK=32, 8 warps (m32 x n64).
// C = Ah*(Bh + Bl). Double-buffered smem, ONE barrier per k-iteration.
// ===========================================================================
#define AS 40
#define BSS 136
#define STG_A (128 * AS)
#define STG_B (32 * BSS)
#define STG_E (STG_A + 2 * STG_B)
#define GEMM_SMEM (2 * STG_E * 2)

struct MmaCtx {
    int wm, wn, l16, grp, lane;
};

__device__ __forceinline__ void mma_kblock(float (&acc)[2][8][4], uint32_t base,
                                           const MmaCtx& c) {
    const uint32_t sAh = base;
    const uint32_t sBh = base + STG_A * 2;
    const uint32_t sBl = base + STG_A * 2 + STG_B * 2;
#pragma unroll
    for (int ks = 0; ks < 32; ks += 16) {
        uint32_t ah[2][4];
#pragma unroll
        for (int mi = 0; mi < 2; ++mi) {
            const uint32_t aoff =
                (uint32_t)(((c.wm + mi * 16 + c.l16) * AS + ks + (c.lane >> 4) * 8) * 2);
            ldsm_x4(ah[mi], sAh + aoff);
        }
        uint32_t bh[8][2], bl[8][2];
#pragma unroll
        for (int nb = 0; nb < 4; ++nb) {
            const uint32_t boff =
                (uint32_t)(((ks + (c.grp & 1) * 8 + (c.lane & 7)) * BSS +
                            c.wn + nb * 16 + (c.grp >> 1) * 8) * 2);
            uint32_t rh[4], rl[4];
            ldsm_x4t(rh, sBh + boff);
            ldsm_x4t(rl, sBl + boff);
            bh[2 * nb][0] = rh[0]; bh[2 * nb][1] = rh[1];
            bh[2 * nb + 1][0] = rh[2]; bh[2 * nb + 1][1] = rh[3];
            bl[2 * nb][0] = rl[0]; bl[2 * nb][1] = rl[1];
            bl[2 * nb + 1][0] = rl[2]; bl[2 * nb + 1][1] = rl[3];
        }
#pragma unroll
        for (int mi = 0; mi < 2; ++mi)
#pragma unroll
            for (int nj = 0; nj < 8; ++nj)
                mma_f16(acc[mi][nj], ah[mi], bh[nj][0], bh[nj][1]);
#pragma unroll
        for (int mi = 0; mi < 2; ++mi)
#pragma unroll
            for (int nj = 0; nj < 8; ++nj)
                mma_f16(acc[mi][nj], ah[mi], bl[nj][0], bl[nj][1]);
    }
}

// ---------------------------------------------------------------------------
// Merged QKV projection: blockIdx.z selects (X, W, out). Double-buffered.
// A = fp16(X) (hi only); B = W split hi/lo. Output q/k/v as fp16 hi/lo.
// ---------------------------------------------------------------------------
struct ProjArgs {
    const float* X[3];
    const float* W[3];
    __half* oh[3];
    __half* ol[3];
};

__global__ __launch_bounds__(256) void proj_mma(ProjArgs args) {
    extern __shared__ __half gsm[];
    const uint32_t smb = smem_u32(gsm);
    const int z = blockIdx.z;
    const float* X = args.X[z];
    const float* W = args.W[z];
    __half* oh = args.oh[z];
    __half* ol = args.ol[z];

    const int tid = threadIdx.x;
    const int wid = tid >> 5, lane = tid & 31;
    MmaCtx c{(wid >> 1) * 32, (wid & 1) * 64, lane & 15, lane >> 3, lane};
    const int r0 = lane >> 2, c2 = (lane & 3) * 2;
    const int row0 = blockIdx.x * 128, c0 = blockIdx.y * 128;

    float acc[2][8][4] = {};
    float4 xr[4];
    float2 wr[8];

    auto load_regs = [&](int kk) {
#pragma unroll
        for (int rep = 0; rep < 4; ++rep) {
            int idx = tid + rep * 256;
            int r = idx >> 3, kc = (idx & 7) * 4;
            xr[rep] = *(const float4*)(X + (size_t)(row0 + r) * Dn + kk + kc);
        }
#pragma unroll
        for (int rep = 0; rep < 8; ++rep) {
            int idx = tid + rep * 256;
            int k = idx >> 6, col = (idx & 63) * 2;
            int colg = c0 + col;
            int h = colg >> 6, kidx = colg & 63;
            wr[rep] = *(const float2*)(W + (size_t)(h * Dn + kk + k) * Kn + kidx);
        }
    };

    load_regs(0);
    for (int it = 0; it < Dn / 32; ++it) {
        const int st = it & 1;
        __half* Ah = gsm + st * STG_E;
        __half* Bh = Ah + STG_A;
        __half* Bl = Bh + STG_B;
#pragma unroll
        for (int rep = 0; rep < 4; ++rep) {
            int idx = tid + rep * 256;
            int r = idx >> 3, kc = (idx & 7) * 4;
            *(uint2*)&Ah[r * AS + kc] =
                make_uint2(pack_h(xr[rep].x, xr[rep].y), pack_h(xr[rep].z, xr[rep].w));
        }
#pragma unroll
        for (int rep = 0; rep < 8; ++rep) {
            int idx = tid + rep * 256;
            int k = idx >> 6, col = (idx & 63) * 2;
            uint32_t bh, bl;
            split2(wr[rep].x, wr[rep].y, bh, bl);
            *(uint32_t*)&Bh[k * BSS + col] = bh;
            *(uint32_t*)&Bl[k * BSS + col] = bl;
        }
        __syncthreads();
        if (it + 1 < Dn / 32) load_regs((it + 1) * 32);
        mma_kblock(acc, smb + (uint32_t)st * (STG_E * 2), c);
    }

#pragma unroll
    for (int mi = 0; mi < 2; ++mi)
#pragma unroll
        for (int rr = 0; rr < 2; ++rr) {
            int row = row0 + c.wm + mi * 16 + r0 + rr * 8;
            int b = row >> 11, s = row & 2047;
#pragma unroll
            for (int nj = 0; nj < 8; ++nj) {
                int colg = c0 + c.wn + nj * 8 + c2;
                int h = colg >> 6, k0 = colg & 63;
                size_t off = (((size_t)(b * Hn + h) * Sn + s) * Kn) + k0;
                uint32_t hv, lv;
                split2(acc[mi][nj][2 * rr], acc[mi][nj][2 * rr + 1], hv, lv);
                *(uint32_t*)(oh + off) = hv;
                *(uint32_t*)(ol + off) = lv;
            }
        }
}

// ---------------------------------------------------------------------------
// Output projection; A = attn output fp16 (hi only); B = Wo split hi/lo.
// ---------------------------------------------------------------------------
__global__ __launch_bounds__(256) void outproj_mma(const __half* __restrict__ Xh,
                                                   const float* __restrict__ Wo,
                                                   float* __restrict__ out) {
    extern __shared__ __half gsm[];
    const uint32_t smb = smem_u32(gsm);

    const int tid = threadIdx.x;
    const int wid = tid >> 5, lane = tid & 31;
    MmaCtx c{(wid >> 1) * 32, (wid & 1) * 64, lane & 15, lane >> 3, lane};
    const int r0 = lane >> 2, c2 = (lane & 3) * 2;
    const int row0 = blockIdx.x * 128, c0 = blockIdx.y * 128;

    float acc[2][8][4] = {};
    uint4 ar[2];
    float2 wr[8];

    auto load_regs = [&](int kk) {
#pragma unroll
        for (int rep = 0; rep < 2; ++rep) {
            int idx = tid + rep * 256;
            int r = idx >> 2, kc = (idx & 3) * 8;
            ar[rep] = *(const uint4*)(Xh + (size_t)(row0 + r) * Dn + kk + kc);
        }
#pragma unroll
        for (int rep = 0; rep < 8; ++rep) {
            int idx = tid + rep * 256;
            int k = idx >> 6, col = (idx & 63) * 2;
            wr[rep] = *(const float2*)(Wo + (size_t)(kk + k) * Dn + c0 + col);
        }
    };

    load_regs(0);
    for (int it = 0; it < Dn / 32; ++it) {
        const int st = it & 1;
        __half* Ah = gsm + st * STG_E;
        __half* Bh = Ah + STG_A;
        __half* Bl = Bh + STG_B;
#pragma unroll
        for (int rep = 0; rep < 2; ++rep) {
            int idx = tid + rep * 256;
            int r = idx >> 2, kc = (idx & 3) * 8;
            *(uint4*)&Ah[r * AS + kc] = ar[rep];
        }
#pragma unroll
        for (int rep = 0; rep < 8; ++rep) {
            int idx = tid + rep * 256;
            int k = idx >> 6, col = (idx & 63) * 2;
            uint32_t bh, bl;
            split2(wr[rep].x, wr[rep].y, bh, bl);
            *(uint32_t*)&Bh[k * BSS + col] = bh;
            *(uint32_t*)&Bl[k * BSS + col] = bl;
        }
        __syncthreads();
        if (it + 1 < Dn / 32) load_regs((it + 1) * 32);
        mma_kblock(acc, smb + (uint32_t)st * (STG_E * 2), c);
    }

#pragma unroll
    for (int mi = 0; mi < 2; ++mi)
#pragma unroll
        for (int rr = 0; rr < 2; ++rr) {
            int row = row0 + c.wm + mi * 16 + r0 + rr * 8;
#pragma unroll
            for (int nj = 0; nj < 8; ++nj) {
                int colg = c0 + c.wn + nj * 8 + c2;
                *(float2*)(out + (size_t)row * Dn + colg) =
                    make_float2(acc[mi][nj][2 * rr], acc[mi][nj][2 * rr + 1]);
            }
        }
}

// ---------------------------------------------------------------------------
extern "C" void kernel_launch(void* const* d_in, const int* in_sizes, int n_in,
                              void* d_out, int out_size) {
    const float* queries = (const float*)d_in[0];
    const float* keys    = (const float*)d_in[1];
    const float* values  = (const float*)d_in[2];
    const float* mask    = (const float*)d_in[3];
    const float* W_q     = (const float*)d_in[4];
    const float* W_k     = (const float*)d_in[5];
    const float* W_v     = (const float*)d_in[6];
    const float* W_o     = (const float*)d_in[7];
    float* out = (float*)d_out;

    __half *qh, *ql, *kh, *kl, *vh, *vl, *oh;
    cudaGetSymbolAddress((void**)&qh, g_qh);
    cudaGetSymbolAddress((void**)&ql, g_ql);
    cudaGetSymbolAddress((void**)&kh, g_kh);
    cudaGetSymbolAddress((void**)&kl, g_kl);
    cudaGetSymbolAddress((void**)&vh, g_vh);
    cudaGetSymbolAddress((void**)&vl, g_vl);
    cudaGetSymbolAddress((void**)&oh, g_oh);

    cudaFuncSetAttribute(attn_kernel, cudaFuncAttributeMaxDynamicSharedMemorySize, ATTN_SMEM);
    cudaFuncSetAttribute(proj_mma, cudaFuncAttributeMaxDynamicSharedMemorySize, GEMM_SMEM);
    cudaFuncSetAttribute(outproj_mma, cudaFuncAttributeMaxDynamicSharedMemorySize, GEMM_SMEM);

    ProjArgs pa;
    pa.X[0] = queries; pa.X[1] = keys; pa.X[2] = values;
    pa.W[0] = W_q;     pa.W[1] = W_k;  pa.W[2] = W_v;
    pa.oh[0] = qh;     pa.oh[1] = kh;  pa.oh[2] = vh;
    pa.ol[0] = ql;     pa.ol[1] = kl;  pa.ol[2] = vl;

    dim3 gproj(Bn * Sn / 128, Dn / 128, 3);  // (64, 6, 3)
    proj_mma<<<gproj, 256, GEMM_SMEM>>>(pa);

    dim3 gattn(Sn / 128, Hn, Bn);  // (16, 12, 4)
    attn_kernel<<<gattn, 512, ATTN_SMEM>>>(mask);

    dim3 gout(Bn * Sn / 128, Dn / 128);  // (64, 6)
    outproj_mma<<<gout, 256, GEMM_SMEM>>>(oh, W_o, out);
}

// round 16
// speedup vs baseline: 1.5375x; 1.0632x over previous
#include <cuda_runtime.h>
#include <cuda_fp16.h>
#include <cstdint>

#define Bn 4
#define Sn 2048
#define Dn 768
#define Hn 12
#define Kn 64
#define NELEM (Bn * Hn * Sn * Kn)

// Scratch device globals (no cudaMalloc allowed). fp16.
__device__ __half g_qh[NELEM];
__device__ __half g_kh[NELEM], g_kl[NELEM];
__device__ __half g_vh[NELEM], g_vl[NELEM];
__device__ __half g_oh[NELEM];
__device__ __half g_ql[NELEM];   // q-lo written by shared proj epilogue, unused

// ---------------------------------------------------------------------------
// helpers
// ---------------------------------------------------------------------------
__device__ __forceinline__ uint32_t smem_u32(const void* p) {
    uint32_t a;
    asm("{ .reg .u64 t; cvta.to.shared.u64 t, %1; cvt.u32.u64 %0, t; }" : "=r"(a) : "l"(p));
    return a;
}
__device__ __forceinline__ void ldsm_x4(uint32_t (&r)[4], uint32_t addr) {
    asm volatile("ldmatrix.sync.aligned.m8n8.x4.shared.b16 {%0,%1,%2,%3}, [%4];"
                 : "=r"(r[0]), "=r"(r[1]), "=r"(r[2]), "=r"(r[3]) : "r"(addr));
}
__device__ __forceinline__ void ldsm_x4t(uint32_t (&r)[4], uint32_t addr) {
    asm volatile("ldmatrix.sync.aligned.m8n8.x4.trans.shared.b16 {%0,%1,%2,%3}, [%4];"
                 : "=r"(r[0]), "=r"(r[1]), "=r"(r[2]), "=r"(r[3]) : "r"(addr));
}
__device__ __forceinline__ void mma_f16(float (&d)[4], const uint32_t (&a)[4],
                                        const uint32_t b0, const uint32_t b1) {
    asm volatile(
        "mma.sync.aligned.m16n8k16.row.col.f32.f16.f16.f32 "
        "{%0,%1,%2,%3}, {%4,%5,%6,%7}, {%8,%9}, {%0,%1,%2,%3};"
        : "+f"(d[0]), "+f"(d[1]), "+f"(d[2]), "+f"(d[3])
        : "r"(a[0]), "r"(a[1]), "r"(a[2]), "r"(a[3]), "r"(b0), "r"(b1));
}
__device__ __forceinline__ void split2(float x, float y, uint32_t& h, uint32_t& l) {
    __half hx = __float2half_rn(x), hy = __float2half_rn(y);
    __half lx = __float2half_rn(x - __half2float(hx));
    __half ly = __float2half_rn(y - __half2float(hy));
    __half2 hh = __halves2half2(hx, hy);
    __half2 ll = __halves2half2(lx, ly);
    h = *(uint32_t*)&hh;
    l = *(uint32_t*)&ll;
}
__device__ __forceinline__ uint32_t pack_h(float x, float y) {
    __half2 hh = __halves2half2(__float2half_rn(x), __float2half_rn(y));
    return *(uint32_t*)&hh;
}
__device__ __forceinline__ void cpa16(uint32_t dst, const void* src) {
    asm volatile("cp.async.cg.shared.global [%0], [%1], 16;" :: "r"(dst), "l"(src) : "memory");
}
__device__ __forceinline__ void cp_commit() { asm volatile("cp.async.commit_group;" ::: "memory"); }
__device__ __forceinline__ void cp_wait1() { asm volatile("cp.async.wait_group 1;" ::: "memory"); }

// ===========================================================================
// Attention: 256 threads / 8 warps. Warp (qw, half): qw = wid>>1 owns q rows
// [32qw, 32qw+32) (two m16 sub-tiles), half = wid&1 owns S cols / kv rows
// [64half, 64half+64). cp.async double buffer, no-max softmax.
// fp16 2-term: S = qh*(kh+kl), O = Ph*(vh+vl). Output: fp16 hi only.
// ===========================================================================
#define QS 72
#define TILE_E (128 * QS)
#define SM_MAXB (10 * TILE_E * 2)
#define ATTN_SMEM (SM_MAXB + 256 * 4)

__global__ __launch_bounds__(256, 1) void attn_kernel(const float* __restrict__ mask) {
    extern __shared__ __half smbf[];
    const uint32_t smb = smem_u32(smbf);
    const uint32_t sQh = smb;
    float* mbuf = (float*)((char*)smbf + SM_MAXB);
    float* Obuf = (float*)(smbf + 2 * TILE_E);

    const int tid = threadIdx.x;
    const int wid = tid >> 5, lane = tid & 31;
    const int qw = wid >> 1, half_i = wid & 1;
    const int cb = half_i * 64;
    const int l16 = lane & 15;
    const int g = lane >> 3;
    const int r0 = lane >> 2;
    const int c2 = (lane & 3) * 2;
    const int qt = blockIdx.x, hd = blockIdx.y, b = blockIdx.z;
    const size_t bh = (size_t)(b * Hn + hd) * Sn;
    const int qr0 = qw * 32;
    const int qg0 = qt * 128 + qr0;

    const int ld_c = (tid & 7) * 8;

    // Q tile hi into smem (once).
    {
        const __half* qh = g_qh + (bh + (size_t)qt * 128) * Kn;
#pragma unroll
        for (int rep = 0; rep < 4; ++rep) {
            int r = (tid + rep * 256) >> 3;
            *(uint4*)(smbf + r * QS + ld_c) = *(const uint4*)(qh + r * 64 + ld_c);
        }
    }

    auto issue_tile = [&](int kt2, int st) {
        const __half* kh = g_kh + (bh + (size_t)kt2 * 128) * Kn;
        const __half* kl = g_kl + (bh + (size_t)kt2 * 128) * Kn;
        const __half* vh = g_vh + (bh + (size_t)kt2 * 128) * Kn;
        const __half* vl = g_vl + (bh + (size_t)kt2 * 128) * Kn;
        const uint32_t base = smb + (uint32_t)(2 + st * 4) * (TILE_E * 2);
#pragma unroll
        for (int rep = 0; rep < 4; ++rep) {
            int r = (tid + rep * 256) >> 3;
            uint32_t off = (uint32_t)(r * QS + ld_c) * 2;
            cpa16(base + off, kh + r * 64 + ld_c);
            cpa16(base + TILE_E * 2 + off, kl + r * 64 + ld_c);
            cpa16(base + TILE_E * 4 + off, vh + r * 64 + ld_c);
            cpa16(base + TILE_E * 6 + off, vl + r * 64 + ld_c);
        }
    };

    issue_tile(0, 0);
    cp_commit();
    issue_tile(1, 1);
    cp_commit();

    float oacc[2][8][4];
#pragma unroll
    for (int mi = 0; mi < 2; ++mi)
#pragma unroll
        for (int n = 0; n < 8; ++n)
#pragma unroll
            for (int j = 0; j < 4; ++j) oacc[mi][n][j] = 0.f;
    float lA[2][2] = {{0.f, 0.f}, {0.f, 0.f}};

    const float* mp[2];
    mp[0] = mask + (size_t)(qg0 + r0) * Sn;
    mp[1] = mp[0] + 16 * Sn;
    const float scale = 0.125f;

    for (int kt = 0; kt < Sn / 128; ++kt) {
        const int st = kt & 1;
        const uint32_t sKh = smb + (uint32_t)(2 + st * 4) * (TILE_E * 2);
        const uint32_t sKl = sKh + TILE_E * 2;
        const uint32_t sVh = sKh + TILE_E * 4;
        const uint32_t sVl = sKh + TILE_E * 6;

        cp_wait1();
        __syncthreads();

        // ---- S = Qh @ (Kh + Kl)^T: m32 x n64, 2 fp16 terms ----
        float sacc[2][8][4];
#pragma unroll
        for (int mi = 0; mi < 2; ++mi)
#pragma unroll
            for (int n = 0; n < 8; ++n)
#pragma unroll
                for (int j = 0; j < 4; ++j) sacc[mi][n][j] = 0.f;

#pragma unroll
        for (int ks = 0; ks < 4; ++ks) {
            uint32_t aqh[2][4];
#pragma unroll
            for (int mi = 0; mi < 2; ++mi) {
                const uint32_t aoff =
                    (uint32_t)(((qr0 + mi * 16 + l16) * QS + ks * 16 + (lane >> 4) * 8) * 2);
                ldsm_x4(aqh[mi], sQh + aoff);
            }
            uint32_t rh[4][4], rl[4][4];
#pragma unroll
            for (int n2 = 0; n2 < 4; ++n2) {
                const uint32_t boff =
                    (uint32_t)(((cb + n2 * 16 + (g >> 1) * 8 + (lane & 7)) * QS +
                                ks * 16 + (g & 1) * 8) * 2);
                ldsm_x4(rh[n2], sKh + boff);
                ldsm_x4(rl[n2], sKl + boff);
            }
#pragma unroll
            for (int mi = 0; mi < 2; ++mi)
#pragma unroll
                for (int n2 = 0; n2 < 4; ++n2) {
                    mma_f16(sacc[mi][2 * n2], aqh[mi], rh[n2][0], rh[n2][1]);
                    mma_f16(sacc[mi][2 * n2 + 1], aqh[mi], rh[n2][2], rh[n2][3]);
                }
#pragma unroll
            for (int mi = 0; mi < 2; ++mi)
#pragma unroll
                for (int n2 = 0; n2 < 4; ++n2) {
                    mma_f16(sacc[mi][2 * n2], aqh[mi], rl[n2][0], rl[n2][1]);
                    mma_f16(sacc[mi][2 * n2 + 1], aqh[mi], rl[n2][2], rl[n2][3]);
                }
        }

        // ---- scale + mask bias + exp (no max subtraction) ----
#pragma unroll
        for (int mi = 0; mi < 2; ++mi)
#pragma unroll
            for (int n = 0; n < 8; ++n) {
                const int col = kt * 128 + cb + n * 8 + c2;
                float2 mv0 = __ldg((const float2*)(mp[mi] + col));
                float2 mv1 = __ldg((const float2*)(mp[mi] + 8 * Sn + col));
                sacc[mi][n][0] = __expf(fmaf(sacc[mi][n][0], scale, (1.f - mv0.x) * -1e9f));
                sacc[mi][n][1] = __expf(fmaf(sacc[mi][n][1], scale, (1.f - mv0.y) * -1e9f));
                sacc[mi][n][2] = __expf(fmaf(sacc[mi][n][2], scale, (1.f - mv1.x) * -1e9f));
                sacc[mi][n][3] = __expf(fmaf(sacc[mi][n][3], scale, (1.f - mv1.y) * -1e9f));
                lA[mi][0] += sacc[mi][n][0] + sacc[mi][n][1];
                lA[mi][1] += sacc[mi][n][2] + sacc[mi][n][3];
            }

        // ---- O += Ph @ (Vh + Vl): m32 x v64, 2 fp16 terms ----
#pragma unroll
        for (int j = 0; j < 4; ++j) {
            uint32_t ah[2][4];
#pragma unroll
            for (int mi = 0; mi < 2; ++mi) {
                ah[mi][0] = pack_h(sacc[mi][2 * j][0], sacc[mi][2 * j][1]);
                ah[mi][1] = pack_h(sacc[mi][2 * j][2], sacc[mi][2 * j][3]);
                ah[mi][2] = pack_h(sacc[mi][2 * j + 1][0], sacc[mi][2 * j + 1][1]);
                ah[mi][3] = pack_h(sacc[mi][2 * j + 1][2], sacc[mi][2 * j + 1][3]);
            }
            uint32_t rh[4][4], rl[4][4];
#pragma unroll
            for (int nv2 = 0; nv2 < 4; ++nv2) {
                const uint32_t voff =
                    (uint32_t)(((cb + j * 16 + (g & 1) * 8 + (lane & 7)) * QS +
                                nv2 * 16 + (g >> 1) * 8) * 2);
                ldsm_x4t(rh[nv2], sVh + voff);
                ldsm_x4t(rl[nv2], sVl + voff);
            }
#pragma unroll
            for (int mi = 0; mi < 2; ++mi)
#pragma unroll
                for (int nv2 = 0; nv2 < 4; ++nv2) {
                    mma_f16(oacc[mi][2 * nv2], ah[mi], rh[nv2][0], rh[nv2][1]);
                    mma_f16(oacc[mi][2 * nv2 + 1], ah[mi], rh[nv2][2], rh[nv2][3]);
                }
#pragma unroll
            for (int mi = 0; mi < 2; ++mi)
#pragma unroll
                for (int nv2 = 0; nv2 < 4; ++nv2) {
                    mma_f16(oacc[mi][2 * nv2], ah[mi], rl[nv2][0], rl[nv2][1]);
                    mma_f16(oacc[mi][2 * nv2 + 1], ah[mi], rl[nv2][2], rl[nv2][3]);
                }
        }

        __syncthreads();
        if (kt + 2 < Sn / 128) issue_tile(kt + 2, st);
        cp_commit();
    }

    // ---- final l reduction, merge halves, normalize, store fp16 hi ----
#pragma unroll
    for (int mi = 0; mi < 2; ++mi)
#pragma unroll
        for (int w = 1; w < 4; w <<= 1) {
            lA[mi][0] += __shfl_xor_sync(0xffffffffu, lA[mi][0], w);
            lA[mi][1] += __shfl_xor_sync(0xffffffffu, lA[mi][1], w);
        }
    {
        float* Ow = Obuf + (size_t)half_i * 128 * 64;
#pragma unroll
        for (int mi = 0; mi < 2; ++mi) {
            const int rb = qr0 + mi * 16 + r0;
#pragma unroll
            for (int nv = 0; nv < 8; ++nv) {
                *(float2*)(Ow + rb * 64 + nv * 8 + c2) =
                    make_float2(oacc[mi][nv][0], oacc[mi][nv][1]);
                *(float2*)(Ow + (rb + 8) * 64 + nv * 8 + c2) =
                    make_float2(oacc[mi][nv][2], oacc[mi][nv][3]);
            }
            if ((lane & 3) == 0) {
                mbuf[rb * 2 + half_i] = lA[mi][0];
                mbuf[(rb + 8) * 2 + half_i] = lA[mi][1];
            }
        }
    }
    __syncthreads();
#pragma unroll
    for (int rep = 0; rep < 16; ++rep) {
        int idx = tid + rep * 256;
        int r = idx >> 5, cc = (idx & 31) * 2;
        float2 a = *(float2*)(Obuf + r * 64 + cc);
        float2 bb = *(float2*)(Obuf + (128 + r) * 64 + cc);
        float inv = 1.f / (mbuf[r * 2] + mbuf[r * 2 + 1]);
        size_t off = (bh + (size_t)(qt * 128 + r)) * Kn + cc;
        *(uint32_t*)(g_oh + off) = pack_h((a.x + bb.x) * inv, (a.y + bb.y) * inv);
    }
}

// ===========================================================================
// mma.sync GEMM core (2-term): C[128 x 128] tile, BK=32, 8 warps (m32 x n64).
// C = Ah*(Bh + Bl). Double-buffered smem, ONE barrier per k-iteration.
// ===========================================================================
#define AS 40
#define BSS 136
#define STG_A (128 * AS)
#define STG_B (32 * BSS)
#define STG_E (STG_A + 2 * STG_B)
#define GEMM_SMEM (2 * STG_E * 2)

struct MmaCtx {
    int wm, wn, l16, grp, lane;
};

__device__ __forceinline__ void mma_kblock(float (&acc)[2][8][4], uint32_t base,
                                           const MmaCtx& c) {
    const uint32_t sAh = base;
    const uint32_t sBh = base + STG_A * 2;
    const uint32_t sBl = base + STG_A * 2 + STG_B * 2;
#pragma unroll
    for (int ks = 0; ks < 32; ks += 16) {
        uint32_t ah[2][4];
#pragma unroll
        for (int mi = 0; mi < 2; ++mi) {
            const uint32_t aoff =
                (uint32_t)(((c.wm + mi * 16 + c.l16) * AS + ks + (c.lane >> 4) * 8) * 2);
            ldsm_x4(ah[mi], sAh + aoff);
        }
        uint32_t bh[8][2], bl[8][2];
#pragma unroll
        for (int nb = 0; nb < 4; ++nb) {
            const uint32_t boff =
                (uint32_t)(((ks + (c.grp & 1) * 8 + (c.lane & 7)) * BSS +
                            c.wn + nb * 16 + (c.grp >> 1) * 8) * 2);
            uint32_t rh[4], rl[4];
            ldsm_x4t(rh, sBh + boff);
            ldsm_x4t(rl, sBl + boff);
            bh[2 * nb][0] = rh[0]; bh[2 * nb][1] = rh[1];
            bh[2 * nb + 1][0] = rh[2]; bh[2 * nb + 1][1] = rh[3];
            bl[2 * nb][0] = rl[0]; bl[2 * nb][1] = rl[1];
            bl[2 * nb + 1][0] = rl[2]; bl[2 * nb + 1][1] = rl[3];
        }
#pragma unroll
        for (int mi = 0; mi < 2; ++mi)
#pragma unroll
            for (int nj = 0; nj < 8; ++nj)
                mma_f16(acc[mi][nj], ah[mi], bh[nj][0], bh[nj][1]);
#pragma unroll
        for (int mi = 0; mi < 2; ++mi)
#pragma unroll
            for (int nj = 0; nj < 8; ++nj)
                mma_f16(acc[mi][nj], ah[mi], bl[nj][0], bl[nj][1]);
    }
}

// ---------------------------------------------------------------------------
// Merged QKV projection: blockIdx.z selects (X, W, out). Double-buffered.
// ---------------------------------------------------------------------------
struct ProjArgs {
    const float* X[3];
    const float* W[3];
    __half* oh[3];
    __half* ol[3];
};

__global__ __launch_bounds__(256) void proj_mma(ProjArgs args) {
    extern __shared__ __half gsm[];
    const uint32_t smb = smem_u32(gsm);
    const int z = blockIdx.z;
    const float* X = args.X[z];
    const float* W = args.W[z];
    __half* oh = args.oh[z];
    __half* ol = args.ol[z];

    const int tid = threadIdx.x;
    const int wid = tid >> 5, lane = tid & 31;
    MmaCtx c{(wid >> 1) * 32, (wid & 1) * 64, lane & 15, lane >> 3, lane};
    const int r0 = lane >> 2, c2 = (lane & 3) * 2;
    const int row0 = blockIdx.x * 128, c0 = blockIdx.y * 128;

    float acc[2][8][4] = {};
    float4 xr[4];
    float2 wr[8];

    auto load_regs = [&](int kk) {
#pragma unroll
        for (int rep = 0; rep < 4; ++rep) {
            int idx = tid + rep * 256;
            int r = idx >> 3, kc = (idx & 7) * 4;
            xr[rep] = *(const float4*)(X + (size_t)(row0 + r) * Dn + kk + kc);
        }
#pragma unroll
        for (int rep = 0; rep < 8; ++rep) {
            int idx = tid + rep * 256;
            int k = idx >> 6, col = (idx & 63) * 2;
            int colg = c0 + col;
            int h = colg >> 6, kidx = colg & 63;
            wr[rep] = *(const float2*)(W + (size_t)(h * Dn + kk + k) * Kn + kidx);
        }
    };

    load_regs(0);
    for (int it = 0; it < Dn / 32; ++it) {
        const int st = it & 1;
        __half* Ah = gsm + st * STG_E;
        __half* Bh = Ah + STG_A;
        __half* Bl = Bh + STG_B;
#pragma unroll
        for (int rep = 0; rep < 4; ++rep) {
            int idx = tid + rep * 256;
            int r = idx >> 3, kc = (idx & 7) * 4;
            *(uint2*)&Ah[r * AS + kc] =
                make_uint2(pack_h(xr[rep].x, xr[rep].y), pack_h(xr[rep].z, xr[rep].w));
        }
#pragma unroll
        for (int rep = 0; rep < 8; ++rep) {
            int idx = tid + rep * 256;
            int k = idx >> 6, col = (idx & 63) * 2;
            uint32_t bh, bl;
            split2(wr[rep].x, wr[rep].y, bh, bl);
            *(uint32_t*)&Bh[k * BSS + col] = bh;
            *(uint32_t*)&Bl[k * BSS + col] = bl;
        }
        __syncthreads();
        if (it + 1 < Dn / 32) load_regs((it + 1) * 32);
        mma_kblock(acc, smb + (uint32_t)st * (STG_E * 2), c);
    }

#pragma unroll
    for (int mi = 0; mi < 2; ++mi)
#pragma unroll
        for (int rr = 0; rr < 2; ++rr) {
            int row = row0 + c.wm + mi * 16 + r0 + rr * 8;
            int b = row >> 11, s = row & 2047;
#pragma unroll
            for (int nj = 0; nj < 8; ++nj) {
                int colg = c0 + c.wn + nj * 8 + c2;
                int h = colg >> 6, k0 = colg & 63;
                size_t off = (((size_t)(b * Hn + h) * Sn + s) * Kn) + k0;
                uint32_t hv, lv;
                split2(acc[mi][nj][2 * rr], acc[mi][nj][2 * rr + 1], hv, lv);
                *(uint32_t*)(oh + off) = hv;
                *(uint32_t*)(ol + off) = lv;
            }
        }
}

// ---------------------------------------------------------------------------
// Output projection; A = attn output fp16 (hi only); B = Wo split hi/lo.
// ---------------------------------------------------------------------------
__global__ __launch_bounds__(256) void outproj_mma(const __half* __restrict__ Xh,
                                                   const float* __restrict__ Wo,
                                                   float* __restrict__ out) {
    extern __shared__ __half gsm[];
    const uint32_t smb = smem_u32(gsm);

    const int tid = threadIdx.x;
    const int wid = tid >> 5, lane = tid & 31;
    MmaCtx c{(wid >> 1) * 32, (wid & 1) * 64, lane & 15, lane >> 3, lane};
    const int r0 = lane >> 2, c2 = (lane & 3) * 2;
    const int row0 = blockIdx.x * 128, c0 = blockIdx.y * 128;

    float acc[2][8][4] = {};
    uint4 ar[2];
    float2 wr[8];

    auto load_regs = [&](int kk) {
#pragma unroll
        for (int rep = 0; rep < 2; ++rep) {
            int idx = tid + rep * 256;
            int r = idx >> 2, kc = (idx & 3) * 8;
            ar[rep] = *(const uint4*)(Xh + (size_t)(row0 + r) * Dn + kk + kc);
        }
#pragma unroll
        for (int rep = 0; rep < 8; ++rep) {
            int idx = tid + rep * 256;
            int k = idx >> 6, col = (idx & 63) * 2;
            wr[rep] = *(const float2*)(Wo + (size_t)(kk + k) * Dn + c0 + col);
        }
    };

    load_regs(0);
    for (int it = 0; it < Dn / 32; ++it) {
        const int st = it & 1;
        __half* Ah = gsm + st * STG_E;
        __half* Bh = Ah + STG_A;
        __half* Bl = Bh + STG_B;
#pragma unroll
        for (int rep = 0; rep < 2; ++rep) {
            int idx = tid + rep * 256;
            int r = idx >> 2, kc = (idx & 3) * 8;
            *(uint4*)&Ah[r * AS + kc] = ar[rep];
        }
#pragma unroll
        for (int rep = 0; rep < 8; ++rep) {
            int idx = tid + rep * 256;
            int k = idx >> 6, col = (idx & 63) * 2;
            uint32_t bh, bl;
            split2(wr[rep].x, wr[rep].y, bh, bl);
            *(uint32_t*)&Bh[k * BSS + col] = bh;
            *(uint32_t*)&Bl[k * BSS + col] = bl;
        }
        __syncthreads();
        if (it + 1 < Dn / 32) load_regs((it + 1) * 32);
        mma_kblock(acc, smb + (uint32_t)st * (STG_E * 2), c);
    }

#pragma unroll
    for (int mi = 0; mi < 2; ++mi)
#pragma unroll
        for (int rr = 0; rr < 2; ++rr) {
            int row = row0 + c.wm + mi * 16 + r0 + rr * 8;
#pragma unroll
            for (int nj = 0; nj < 8; ++nj) {
                int colg = c0 + c.wn + nj * 8 + c2;
                *(float2*)(out + (size_t)row * Dn + colg) =
                    make_float2(acc[mi][nj][2 * rr], acc[mi][nj][2 * rr + 1]);
            }
        }
}

// ---------------------------------------------------------------------------
extern "C" void kernel_launch(void* const* d_in, const int* in_sizes, int n_in,
                              void* d_out, int out_size) {
    const float* queries = (const float*)d_in[0];
    const float* keys    = (const float*)d_in[1];
    const float* values  = (const float*)d_in[2];
    const float* mask    = (const float*)d_in[3];
    const float* W_q     = (const float*)d_in[4];
    const float* W_k     = (const float*)d_in[5];
    const float* W_v     = (const float*)d_in[6];
    const float* W_o     = (const float*)d_in[7];
    float* out = (float*)d_out;

    __half *qh, *ql, *kh, *kl, *vh, *vl, *oh;
    cudaGetSymbolAddress((void**)&qh, g_qh);
    cudaGetSymbolAddress((void**)&ql, g_ql);
    cudaGetSymbolAddress((void**)&kh, g_kh);
    cudaGetSymbolAddress((void**)&kl, g_kl);
    cudaGetSymbolAddress((void**)&vh, g_vh);
    cudaGetSymbolAddress((void**)&vl, g_vl);
    cudaGetSymbolAddress((void**)&oh, g_oh);

    cudaFuncSetAttribute(attn_kernel, cudaFuncAttributeMaxDynamicSharedMemorySize, ATTN_SMEM);
    cudaFuncSetAttribute(proj_mma, cudaFuncAttributeMaxDynamicSharedMemorySize, GEMM_SMEM);
    cudaFuncSetAttribute(outproj_mma, cudaFuncAttributeMaxDynamicSharedMemorySize, GEMM_SMEM);

    ProjArgs pa;
    pa.X[0] = queries; pa.X[1] = keys; pa.X[2] = values;
    pa.W[0] = W_q;     pa.W[1] = W_k;  pa.W[2] = W_v;
    pa.oh[0] = qh;     pa.oh[1] = kh;  pa.oh[2] = vh;
    pa.ol[0] = ql;     pa.ol[1] = kl;  pa.ol[2] = vl;

    dim3 gproj(Bn * Sn / 128, Dn / 128, 3);  // (64, 6, 3)
    proj_mma<<<gproj, 256, GEMM_SMEM>>>(pa);

    dim3 gattn(Sn / 128, Hn, Bn);  // (16, 12, 4)
    attn_kernel<<<gattn, 256, ATTN_SMEM>>>(mask);

    dim3 gout(Bn * Sn / 128, Dn / 128);  // (64, 6)
    outproj_mma<<<gout, 256, GEMM_SMEM>>>(oh, W_o, out);
}

// round 17
// speedup vs baseline: 1.5534x; 1.0103x over previous
#include <cuda_runtime.h>
#include <cuda_fp16.h>
#include <cstdint>

#define Bn 4
#define Sn 2048
#define Dn 768
#define Hn 12
#define Kn 64
#define NELEM (Bn * Hn * Sn * Kn)

// Scratch device globals (no cudaMalloc allowed). fp16.
__device__ __half g_qh[NELEM];
__device__ __half g_kh[NELEM], g_kl[NELEM];
__device__ __half g_vh[NELEM], g_vl[NELEM];
__device__ __half g_oh[NELEM];
__device__ __half g_ql[NELEM];                 // q-lo from shared proj epilogue, unused
__device__ __half g_wh[4 * Dn * Dn], g_wl[4 * Dn * Dn];  // presplit W_q,W_k,W_v,W_o

// ---------------------------------------------------------------------------
// helpers
// ---------------------------------------------------------------------------
__device__ __forceinline__ uint32_t smem_u32(const void* p) {
    uint32_t a;
    asm("{ .reg .u64 t; cvta.to.shared.u64 t, %1; cvt.u32.u64 %0, t; }" : "=r"(a) : "l"(p));
    return a;
}
__device__ __forceinline__ void ldsm_x4(uint32_t (&r)[4], uint32_t addr) {
    asm volatile("ldmatrix.sync.aligned.m8n8.x4.shared.b16 {%0,%1,%2,%3}, [%4];"
                 : "=r"(r[0]), "=r"(r[1]), "=r"(r[2]), "=r"(r[3]) : "r"(addr));
}
__device__ __forceinline__ void ldsm_x4t(uint32_t (&r)[4], uint32_t addr) {
    asm volatile("ldmatrix.sync.aligned.m8n8.x4.trans.shared.b16 {%0,%1,%2,%3}, [%4];"
                 : "=r"(r[0]), "=r"(r[1]), "=r"(r[2]), "=r"(r[3]) : "r"(addr));
}
__device__ __forceinline__ void mma_f16(float (&d)[4], const uint32_t (&a)[4],
                                        const uint32_t b0, const uint32_t b1) {
    asm volatile(
        "mma.sync.aligned.m16n8k16.row.col.f32.f16.f16.f32 "
        "{%0,%1,%2,%3}, {%4,%5,%6,%7}, {%8,%9}, {%0,%1,%2,%3};"
        : "+f"(d[0]), "+f"(d[1]), "+f"(d[2]), "+f"(d[3])
        : "r"(a[0]), "r"(a[1]), "r"(a[2]), "r"(a[3]), "r"(b0), "r"(b1));
}
__device__ __forceinline__ void split2(float x, float y, uint32_t& h, uint32_t& l) {
    __half hx = __float2half_rn(x), hy = __float2half_rn(y);
    __half lx = __float2half_rn(x - __half2float(hx));
    __half ly = __float2half_rn(y - __half2float(hy));
    __half2 hh = __halves2half2(hx, hy);
    __half2 ll = __halves2half2(lx, ly);
    h = *(uint32_t*)&hh;
    l = *(uint32_t*)&ll;
}
__device__ __forceinline__ uint32_t pack_h(float x, float y) {
    __half2 hh = __halves2half2(__float2half_rn(x), __float2half_rn(y));
    return *(uint32_t*)&hh;
}
__device__ __forceinline__ void cpa16(uint32_t dst, const void* src) {
    asm volatile("cp.async.cg.shared.global [%0], [%1], 16;" :: "r"(dst), "l"(src) : "memory");
}
__device__ __forceinline__ void cp_commit() { asm volatile("cp.async.commit_group;" ::: "memory"); }
__device__ __forceinline__ void cp_wait1() { asm volatile("cp.async.wait_group 1;" ::: "memory"); }

// ---------------------------------------------------------------------------
// W presplit kernels (run once, tiny).
// W [H][D][K] -> Wt [D][H*K] fp16 hi/lo (proj layout).
// ---------------------------------------------------------------------------
__global__ void split_wqkv(const float* __restrict__ W, __half* __restrict__ wh,
                           __half* __restrict__ wl) {
    int i = blockIdx.x * 256 + threadIdx.x;
    if (i >= Dn * (Dn / 2)) return;
    int d = i / (Dn / 2), c = (i % (Dn / 2)) * 2;
    int h = c >> 6, k = c & 63;
    float2 v = *(const float2*)(W + ((size_t)h * Dn + d) * Kn + k);
    uint32_t hh, ll;
    split2(v.x, v.y, hh, ll);
    *(uint32_t*)(wh + (size_t)d * Dn + c) = hh;
    *(uint32_t*)(wl + (size_t)d * Dn + c) = ll;
}
__global__ void split_wo(const float* __restrict__ W, __half* __restrict__ wh,
                         __half* __restrict__ wl) {
    int i = blockIdx.x * 256 + threadIdx.x;
    if (i >= Dn * (Dn / 2)) return;
    float2 v = ((const float2*)W)[i];
    uint32_t hh, ll;
    split2(v.x, v.y, hh, ll);
    ((uint32_t*)wh)[i] = hh;
    ((uint32_t*)wl)[i] = ll;
}

// ===========================================================================
// Attention (R16 winner, unchanged): 256 threads / 8 warps, m32 warp q-tiles,
// cp.async double buffer, no-max softmax, fp16 2-term splits.
// ===========================================================================
#define QS 72
#define TILE_E (128 * QS)
#define SM_MAXB (10 * TILE_E * 2)
#define ATTN_SMEM (SM_MAXB + 256 * 4)

__global__ __launch_bounds__(256, 1) void attn_kernel(const float* __restrict__ mask) {
    extern __shared__ __half smbf[];
    const uint32_t smb = smem_u32(smbf);
    const uint32_t sQh = smb;
    float* mbuf = (float*)((char*)smbf + SM_MAXB);
    float* Obuf = (float*)(smbf + 2 * TILE_E);

    const int tid = threadIdx.x;
    const int wid = tid >> 5, lane = tid & 31;
    const int qw = wid >> 1, half_i = wid & 1;
    const int cb = half_i * 64;
    const int l16 = lane & 15;
    const int g = lane >> 3;
    const int r0 = lane >> 2;
    const int c2 = (lane & 3) * 2;
    const int qt = blockIdx.x, hd = blockIdx.y, b = blockIdx.z;
    const size_t bh = (size_t)(b * Hn + hd) * Sn;
    const int qr0 = qw * 32;
    const int qg0 = qt * 128 + qr0;

    const int ld_c = (tid & 7) * 8;

    {
        const __half* qh = g_qh + (bh + (size_t)qt * 128) * Kn;
#pragma unroll
        for (int rep = 0; rep < 4; ++rep) {
            int r = (tid + rep * 256) >> 3;
            *(uint4*)(smbf + r * QS + ld_c) = *(const uint4*)(qh + r * 64 + ld_c);
        }
    }

    auto issue_tile = [&](int kt2, int st) {
        const __half* kh = g_kh + (bh + (size_t)kt2 * 128) * Kn;
        const __half* kl = g_kl + (bh + (size_t)kt2 * 128) * Kn;
        const __half* vh = g_vh + (bh + (size_t)kt2 * 128) * Kn;
        const __half* vl = g_vl + (bh + (size_t)kt2 * 128) * Kn;
        const uint32_t base = smb + (uint32_t)(2 + st * 4) * (TILE_E * 2);
#pragma unroll
        for (int rep = 0; rep < 4; ++rep) {
            int r = (tid + rep * 256) >> 3;
            uint32_t off = (uint32_t)(r * QS + ld_c) * 2;
            cpa16(base + off, kh + r * 64 + ld_c);
            cpa16(base + TILE_E * 2 + off, kl + r * 64 + ld_c);
            cpa16(base + TILE_E * 4 + off, vh + r * 64 + ld_c);
            cpa16(base + TILE_E * 6 + off, vl + r * 64 + ld_c);
        }
    };

    issue_tile(0, 0);
    cp_commit();
    issue_tile(1, 1);
    cp_commit();

    float oacc[2][8][4];
#pragma unroll
    for (int mi = 0; mi < 2; ++mi)
#pragma unroll
        for (int n = 0; n < 8; ++n)
#pragma unroll
            for (int j = 0; j < 4; ++j) oacc[mi][n][j] = 0.f;
    float lA[2][2] = {{0.f, 0.f}, {0.f, 0.f}};

    const float* mp[2];
    mp[0] = mask + (size_t)(qg0 + r0) * Sn;
    mp[1] = mp[0] + 16 * Sn;
    const float scale = 0.125f;

    for (int kt = 0; kt < Sn / 128; ++kt) {
        const int st = kt & 1;
        const uint32_t sKh = smb + (uint32_t)(2 + st * 4) * (TILE_E * 2);
        const uint32_t sKl = sKh + TILE_E * 2;
        const uint32_t sVh = sKh + TILE_E * 4;
        const uint32_t sVl = sKh + TILE_E * 6;

        cp_wait1();
        __syncthreads();

        float sacc[2][8][4];
#pragma unroll
        for (int mi = 0; mi < 2; ++mi)
#pragma unroll
            for (int n = 0; n < 8; ++n)
#pragma unroll
                for (int j = 0; j < 4; ++j) sacc[mi][n][j] = 0.f;

#pragma unroll
        for (int ks = 0; ks < 4; ++ks) {
            uint32_t aqh[2][4];
#pragma unroll
            for (int mi = 0; mi < 2; ++mi) {
                const uint32_t aoff =
                    (uint32_t)(((qr0 + mi * 16 + l16) * QS + ks * 16 + (lane >> 4) * 8) * 2);
                ldsm_x4(aqh[mi], sQh + aoff);
            }
            uint32_t rh[4][4], rl[4][4];
#pragma unroll
            for (int n2 = 0; n2 < 4; ++n2) {
                const uint32_t boff =
                    (uint32_t)(((cb + n2 * 16 + (g >> 1) * 8 + (lane & 7)) * QS +
                                ks * 16 + (g & 1) * 8) * 2);
                ldsm_x4(rh[n2], sKh + boff);
                ldsm_x4(rl[n2], sKl + boff);
            }
#pragma unroll
            for (int mi = 0; mi < 2; ++mi)
#pragma unroll
                for (int n2 = 0; n2 < 4; ++n2) {
                    mma_f16(sacc[mi][2 * n2], aqh[mi], rh[n2][0], rh[n2][1]);
                    mma_f16(sacc[mi][2 * n2 + 1], aqh[mi], rh[n2][2], rh[n2][3]);
                }
#pragma unroll
            for (int mi = 0; mi < 2; ++mi)
#pragma unroll
                for (int n2 = 0; n2 < 4; ++n2) {
                    mma_f16(sacc[mi][2 * n2], aqh[mi], rl[n2][0], rl[n2][1]);
                    mma_f16(sacc[mi][2 * n2 + 1], aqh[mi], rl[n2][2], rl[n2][3]);
                }
        }

#pragma unroll
        for (int mi = 0; mi < 2; ++mi)
#pragma unroll
            for (int n = 0; n < 8; ++n) {
                const int col = kt * 128 + cb + n * 8 + c2;
                float2 mv0 = __ldg((const float2*)(mp[mi] + col));
                float2 mv1 = __ldg((const float2*)(mp[mi] + 8 * Sn + col));
                sacc[mi][n][0] = __expf(fmaf(sacc[mi][n][0], scale, (1.f - mv0.x) * -1e9f));
                sacc[mi][n][1] = __expf(fmaf(sacc[mi][n][1], scale, (1.f - mv0.y) * -1e9f));
                sacc[mi][n][2] = __expf(fmaf(sacc[mi][n][2], scale, (1.f - mv1.x) * -1e9f));
                sacc[mi][n][3] = __expf(fmaf(sacc[mi][n][3], scale, (1.f - mv1.y) * -1e9f));
                lA[mi][0] += sacc[mi][n][0] + sacc[mi][n][1];
                lA[mi][1] += sacc[mi][n][2] + sacc[mi][n][3];
            }

#pragma unroll
        for (int j = 0; j < 4; ++j) {
            uint32_t ah[2][4];
#pragma unroll
            for (int mi = 0; mi < 2; ++mi) {
                ah[mi][0] = pack_h(sacc[mi][2 * j][0], sacc[mi][2 * j][1]);
                ah[mi][1] = pack_h(sacc[mi][2 * j][2], sacc[mi][2 * j][3]);
                ah[mi][2] = pack_h(sacc[mi][2 * j + 1][0], sacc[mi][2 * j + 1][1]);
                ah[mi][3] = pack_h(sacc[mi][2 * j + 1][2], sacc[mi][2 * j + 1][3]);
            }
            uint32_t rh[4][4], rl[4][4];
#pragma unroll
            for (int nv2 = 0; nv2 < 4; ++nv2) {
                const uint32_t voff =
                    (uint32_t)(((cb + j * 16 + (g & 1) * 8 + (lane & 7)) * QS +
                                nv2 * 16 + (g >> 1) * 8) * 2);
                ldsm_x4t(rh[nv2], sVh + voff);
                ldsm_x4t(rl[nv2], sVl + voff);
            }
#pragma unroll
            for (int mi = 0; mi < 2; ++mi)
#pragma unroll
                for (int nv2 = 0; nv2 < 4; ++nv2) {
                    mma_f16(oacc[mi][2 * nv2], ah[mi], rh[nv2][0], rh[nv2][1]);
                    mma_f16(oacc[mi][2 * nv2 + 1], ah[mi], rh[nv2][2], rh[nv2][3]);
                }
#pragma unroll
            for (int mi = 0; mi < 2; ++mi)
#pragma unroll
                for (int nv2 = 0; nv2 < 4; ++nv2) {
                    mma_f16(oacc[mi][2 * nv2], ah[mi], rl[nv2][0], rl[nv2][1]);
                    mma_f16(oacc[mi][2 * nv2 + 1], ah[mi], rl[nv2][2], rl[nv2][3]);
                }
        }

        __syncthreads();
        if (kt + 2 < Sn / 128) issue_tile(kt + 2, st);
        cp_commit();
    }

#pragma unroll
    for (int mi = 0; mi < 2; ++mi)
#pragma unroll
        for (int w = 1; w < 4; w <<= 1) {
            lA[mi][0] += __shfl_xor_sync(0xffffffffu, lA[mi][0], w);
            lA[mi][1] += __shfl_xor_sync(0xffffffffu, lA[mi][1], w);
        }
    {
        float* Ow = Obuf + (size_t)half_i * 128 * 64;
#pragma unroll
        for (int mi = 0; mi < 2; ++mi) {
            const int rb = qr0 + mi * 16 + r0;
#pragma unroll
            for (int nv = 0; nv < 8; ++nv) {
                *(float2*)(Ow + rb * 64 + nv * 8 + c2) =
                    make_float2(oacc[mi][nv][0], oacc[mi][nv][1]);
                *(float2*)(Ow + (rb + 8) * 64 + nv * 8 + c2) =
                    make_float2(oacc[mi][nv][2], oacc[mi][nv][3]);
            }
            if ((lane & 3) == 0) {
                mbuf[rb * 2 + half_i] = lA[mi][0];
                mbuf[(rb + 8) * 2 + half_i] = lA[mi][1];
            }
        }
    }
    __syncthreads();
#pragma unroll
    for (int rep = 0; rep < 16; ++rep) {
        int idx = tid + rep * 256;
        int r = idx >> 5, cc = (idx & 31) * 2;
        float2 a = *(float2*)(Obuf + r * 64 + cc);
        float2 bb = *(float2*)(Obuf + (128 + r) * 64 + cc);
        float inv = 1.f / (mbuf[r * 2] + mbuf[r * 2 + 1]);
        size_t off = (bh + (size_t)(qt * 128 + r)) * Kn + cc;
        *(uint32_t*)(g_oh + off) = pack_h((a.x + bb.x) * inv, (a.y + bb.y) * inv);
    }
}

// ===========================================================================
// mma.sync GEMM core (2-term): C[128 x 128] tile, BK=32, 8 warps (m32 x n64).
// C = Ah*(Bh + Bl). A and B bases passed separately.
// ===========================================================================
#define AS 40
#define BSS 136
#define STG_A (128 * AS)
#define STG_B (32 * BSS)
#define PROJ_SMEM ((2 * STG_A + 6 * STG_B) * 2)
#define OSTG (STG_A + 2 * STG_B)
#define OUT_SMEM (3 * OSTG * 2)

struct MmaCtx {
    int wm, wn, l16, grp, lane;
};

__device__ __forceinline__ void mma_kblock(float (&acc)[2][8][4], uint32_t aBase,
                                           uint32_t bBase, const MmaCtx& c) {
    const uint32_t sBh = bBase;
    const uint32_t sBl = bBase + STG_B * 2;
#pragma unroll
    for (int ks = 0; ks < 32; ks += 16) {
        uint32_t ah[2][4];
#pragma unroll
        for (int mi = 0; mi < 2; ++mi) {
            const uint32_t aoff =
                (uint32_t)(((c.wm + mi * 16 + c.l16) * AS + ks + (c.lane >> 4) * 8) * 2);
            ldsm_x4(ah[mi], aBase + aoff);
        }
        uint32_t bh[8][2], bl[8][2];
#pragma unroll
        for (int nb = 0; nb < 4; ++nb) {
            const uint32_t boff =
                (uint32_t)(((ks + (c.grp & 1) * 8 + (c.lane & 7)) * BSS +
                            c.wn + nb * 16 + (c.grp >> 1) * 8) * 2);
            uint32_t rh[4], rl[4];
            ldsm_x4t(rh, sBh + boff);
            ldsm_x4t(rl, sBl + boff);
            bh[2 * nb][0] = rh[0]; bh[2 * nb][1] = rh[1];
            bh[2 * nb + 1][0] = rh[2]; bh[2 * nb + 1][1] = rh[3];
            bl[2 * nb][0] = rl[0]; bl[2 * nb][1] = rl[1];
            bl[2 * nb + 1][0] = rl[2]; bl[2 * nb + 1][1] = rl[3];
        }
#pragma unroll
        for (int mi = 0; mi < 2; ++mi)
#pragma unroll
            for (int nj = 0; nj < 8; ++nj)
                mma_f16(acc[mi][nj], ah[mi], bh[nj][0], bh[nj][1]);
#pragma unroll
        for (int mi = 0; mi < 2; ++mi)
#pragma unroll
            for (int nj = 0; nj < 8; ++nj)
                mma_f16(acc[mi][nj], ah[mi], bl[nj][0], bl[nj][1]);
    }
}

// ---------------------------------------------------------------------------
// Merged QKV projection. A (X fp32) register-staged 2-stage + packed to fp16.
// B (presplit W fp16) streams via cp.async in a 3-stage ring. 1 barrier/iter.
// ---------------------------------------------------------------------------
struct ProjArgs {
    const float* X[3];
    const __half* Wh[3];
    const __half* Wl[3];
    __half* oh[3];
    __half* ol[3];
};

__global__ __launch_bounds__(256) void proj_mma(ProjArgs args) {
    extern __shared__ __half gsm[];
    const uint32_t smb = smem_u32(gsm);
    const int z = blockIdx.z;
    const float* X = args.X[z];
    const __half* Wh = args.Wh[z];
    const __half* Wl = args.Wl[z];
    __half* oh = args.oh[z];
    __half* ol = args.ol[z];

    const int tid = threadIdx.x;
    const int wid = tid >> 5, lane = tid & 31;
    MmaCtx c{(wid >> 1) * 32, (wid & 1) * 64, lane & 15, lane >> 3, lane};
    const int r0 = lane >> 2, c2 = (lane & 3) * 2;
    const int row0 = blockIdx.x * 128, c0 = blockIdx.y * 128;

    float acc[2][8][4] = {};
    float4 xr[4];

    auto load_A = [&](int kk) {
#pragma unroll
        for (int rep = 0; rep < 4; ++rep) {
            int idx = tid + rep * 256;
            int r = idx >> 3, kc = (idx & 7) * 4;
            xr[rep] = *(const float4*)(X + (size_t)(row0 + r) * Dn + kk + kc);
        }
    };
    auto issue_B = [&](int it2) {
        const int bst = it2 % 3;
        const __half* srcH = Wh + (size_t)(it2 * 32) * Dn + c0;
        const __half* srcL = Wl + (size_t)(it2 * 32) * Dn + c0;
        const uint32_t bbase = smb + (uint32_t)(2 * STG_A + bst * 2 * STG_B) * 2;
#pragma unroll
        for (int rep = 0; rep < 2; ++rep) {
            int idx = tid + rep * 256;
            int r = idx >> 4, cc = (idx & 15) * 8;
            uint32_t off = (uint32_t)(r * BSS + cc) * 2;
            cpa16(bbase + off, srcH + (size_t)r * Dn + cc);
            cpa16(bbase + STG_B * 2 + off, srcL + (size_t)r * Dn + cc);
        }
    };

    issue_B(0);
    cp_commit();
    issue_B(1);
    cp_commit();
    load_A(0);

    for (int it = 0; it < Dn / 32; ++it) {
        const int ast = it & 1, bst = it % 3;
        __half* Ah = gsm + ast * STG_A;
#pragma unroll
        for (int rep = 0; rep < 4; ++rep) {
            int idx = tid + rep * 256;
            int r = idx >> 3, kc = (idx & 7) * 4;
            *(uint2*)&Ah[r * AS + kc] =
                make_uint2(pack_h(xr[rep].x, xr[rep].y), pack_h(xr[rep].z, xr[rep].w));
        }
        cp_wait1();
        __syncthreads();
        if (it + 2 < Dn / 32) issue_B(it + 2);
        cp_commit();
        if (it + 1 < Dn / 32) load_A((it + 1) * 32);
        mma_kblock(acc, smb + (uint32_t)ast * STG_A * 2,
                   smb + (uint32_t)(2 * STG_A + bst * 2 * STG_B) * 2, c);
    }

#pragma unroll
    for (int mi = 0; mi < 2; ++mi)
#pragma unroll
        for (int rr = 0; rr < 2; ++rr) {
            int row = row0 + c.wm + mi * 16 + r0 + rr * 8;
            int b = row >> 11, s = row & 2047;
#pragma unroll
            for (int nj = 0; nj < 8; ++nj) {
                int colg = c0 + c.wn + nj * 8 + c2;
                int h = colg >> 6, k0 = colg & 63;
                size_t off = (((size_t)(b * Hn + h) * Sn + s) * Kn) + k0;
                uint32_t hv, lv;
                split2(acc[mi][nj][2 * rr], acc[mi][nj][2 * rr + 1], hv, lv);
                *(uint32_t*)(oh + off) = hv;
                *(uint32_t*)(ol + off) = lv;
            }
        }
}

// ---------------------------------------------------------------------------
// Output projection: A (attn out fp16) and B (presplit Wo fp16) both via
// cp.async in a 3-stage ring. 1 barrier/iter.
// ---------------------------------------------------------------------------
__global__ __launch_bounds__(256) void outproj_mma(const __half* __restrict__ Xh,
                                                   const __half* __restrict__ Woh,
                                                   const __half* __restrict__ Wol,
                                                   float* __restrict__ out) {
    extern __shared__ __half gsm[];
    const uint32_t smb = smem_u32(gsm);

    const int tid = threadIdx.x;
    const int wid = tid >> 5, lane = tid & 31;
    MmaCtx c{(wid >> 1) * 32, (wid & 1) * 64, lane & 15, lane >> 3, lane};
    const int r0 = lane >> 2, c2 = (lane & 3) * 2;
    const int row0 = blockIdx.x * 128, c0 = blockIdx.y * 128;

    float acc[2][8][4] = {};

    auto issue = [&](int it2) {
        const int st = it2 % 3;
        const int kk = it2 * 32;
        const uint32_t base = smb + (uint32_t)(st * OSTG) * 2;
#pragma unroll
        for (int rep = 0; rep < 2; ++rep) {
            int idx = tid + rep * 256;
            int r = idx >> 2, cc = (idx & 3) * 8;
            cpa16(base + (uint32_t)(r * AS + cc) * 2,
                  Xh + (size_t)(row0 + r) * Dn + kk + cc);
        }
#pragma unroll
        for (int rep = 0; rep < 2; ++rep) {
            int idx = tid + rep * 256;
            int r = idx >> 4, cc = (idx & 15) * 8;
            uint32_t off = (uint32_t)(r * BSS + cc) * 2;
            cpa16(base + STG_A * 2 + off, Woh + (size_t)(kk + r) * Dn + c0 + cc);
            cpa16(base + STG_A * 2 + STG_B * 2 + off, Wol + (size_t)(kk + r) * Dn + c0 + cc);
        }
    };

    issue(0);
    cp_commit();
    issue(1);
    cp_commit();

    for (int it = 0; it < Dn / 32; ++it) {
        const int st = it % 3;
        cp_wait1();
        __syncthreads();
        if (it + 2 < Dn / 32) issue(it + 2);
        cp_commit();
        const uint32_t base = smb + (uint32_t)(st * OSTG) * 2;
        mma_kblock(acc, base, base + STG_A * 2, c);
    }

#pragma unroll
    for (int mi = 0; mi < 2; ++mi)
#pragma unroll
        for (int rr = 0; rr < 2; ++rr) {
            int row = row0 + c.wm + mi * 16 + r0 + rr * 8;
#pragma unroll
            for (int nj = 0; nj < 8; ++nj) {
                int colg = c0 + c.wn + nj * 8 + c2;
                *(float2*)(out + (size_t)row * Dn + colg) =
                    make_float2(acc[mi][nj][2 * rr], acc[mi][nj][2 * rr + 1]);
            }
        }
}

// ---------------------------------------------------------------------------
extern "C" void kernel_launch(void* const* d_in, const int* in_sizes, int n_in,
                              void* d_out, int out_size) {
    const float* queries = (const float*)d_in[0];
    const float* keys    = (const float*)d_in[1];
    const float* values  = (const float*)d_in[2];
    const float* mask    = (const float*)d_in[3];
    const float* W_q     = (const float*)d_in[4];
    const float* W_k     = (const float*)d_in[5];
    const float* W_v     = (const float*)d_in[6];
    const float* W_o     = (const float*)d_in[7];
    float* out = (float*)d_out;

    __half *qh, *ql, *kh, *kl, *vh, *vl, *oh, *wh, *wl;
    cudaGetSymbolAddress((void**)&qh, g_qh);
    cudaGetSymbolAddress((void**)&ql, g_ql);
    cudaGetSymbolAddress((void**)&kh, g_kh);
    cudaGetSymbolAddress((void**)&kl, g_kl);
    cudaGetSymbolAddress((void**)&vh, g_vh);
    cudaGetSymbolAddress((void**)&vl, g_vl);
    cudaGetSymbolAddress((void**)&oh, g_oh);
    cudaGetSymbolAddress((void**)&wh, g_wh);
    cudaGetSymbolAddress((void**)&wl, g_wl);

    cudaFuncSetAttribute(attn_kernel, cudaFuncAttributeMaxDynamicSharedMemorySize, ATTN_SMEM);
    cudaFuncSetAttribute(proj_mma, cudaFuncAttributeMaxDynamicSharedMemorySize, PROJ_SMEM);
    cudaFuncSetAttribute(outproj_mma, cudaFuncAttributeMaxDynamicSharedMemorySize, OUT_SMEM);

    const int nsplit = (Dn * (Dn / 2) + 255) / 256;
    split_wqkv<<<nsplit, 256>>>(W_q, wh + 0 * Dn * Dn, wl + 0 * Dn * Dn);
    split_wqkv<<<nsplit, 256>>>(W_k, wh + 1 * Dn * Dn, wl + 1 * Dn * Dn);
    split_wqkv<<<nsplit, 256>>>(W_v, wh + 2 * Dn * Dn, wl + 2 * Dn * Dn);
    split_wo<<<nsplit, 256>>>(W_o, wh + 3 * Dn * Dn, wl + 3 * Dn * Dn);

    ProjArgs pa;
    pa.X[0] = queries; pa.X[1] = keys; pa.X[2] = values;
    pa.Wh[0] = wh;              pa.Wl[0] = wl;
    pa.Wh[1] = wh + Dn * Dn;    pa.Wl[1] = wl + Dn * Dn;
    pa.Wh[2] = wh + 2 * Dn * Dn; pa.Wl[2] = wl + 2 * Dn * Dn;
    pa.oh[0] = qh; pa.oh[1] = kh; pa.oh[2] = vh;
    pa.ol[0] = ql; pa.ol[1] = kl; pa.ol[2] = vl;

    dim3 gproj(Bn * Sn / 128, Dn / 128, 3);  // (64, 6, 3)
    proj_mma<<<gproj, 256, PROJ_SMEM>>>(pa);

    dim3 gattn(Sn / 128, Hn, Bn);  // (16, 12, 4)
    attn_kernel<<<gattn, 256, ATTN_SMEM>>>(mask);

    dim3 gout(Bn * Sn / 128, Dn / 128);  // (64, 6)
    outproj_mma<<<gout, 256, OUT_SMEM>>>(oh, wh + 3 * Dn * Dn, wl + 3 * Dn * Dn, out);
}